// round 1
// baseline (speedup 1.0000x reference)
#include <cuda_runtime.h>
#include <math.h>

// Problem dims (fixed by reference)
#define B_   4
#define S_   2048
#define H_   1024
#define F_   4096
#define NTOK (B_ * S_)   // 8192

// ---------------------------------------------------------------------------
// Scratch (static device globals -- no allocation allowed in kernel_launch)
// ---------------------------------------------------------------------------
__device__ float g_q[(size_t)NTOK * H_];
__device__ float g_k[(size_t)NTOK * H_];
__device__ float g_v[(size_t)NTOK * H_];
__device__ float g_s[(size_t)B_ * S_ * S_];
__device__ float g_attn[(size_t)NTOK * H_];
__device__ float g_h[(size_t)NTOK * F_];
__device__ float g_y[(size_t)NTOK * H_];

// ---------------------------------------------------------------------------
// Generic tiled SGEMM: C = alpha * A * op(B) (+ bias) (+ res) (relu)
//   A: [M,K] row-major, lda
//   B: NN -> [K,N] row-major, ldb ; BT -> [N,K] row-major, ldb (computes A*B^T)
//   Batched over blockIdx.z with element strides sA/sB/sC (residual shares sC).
//   All of M,N multiples of 128; K multiple of 8; all lds multiples of 4.
// ---------------------------------------------------------------------------
template <bool BT, bool BIAS, bool RELU, bool RES>
__global__ __launch_bounds__(256) void gemm_k(
    const float* __restrict__ A, const float* __restrict__ Bm,
    const float* __restrict__ bias, const float* __restrict__ res,
    float* __restrict__ C,
    int M, int N, int K, int lda, int ldb, int ldc,
    size_t sA, size_t sB, size_t sC, float alpha)
{
    constexpr int BM = 128, BN = 128, BK = 8, TM = 8, TN = 8;
    __shared__ float As[BK * BM];   // transposed: As[k][m]
    __shared__ float Bs[BK * BN];   // Bs[k][n]

    const int z = blockIdx.z;
    A  += (size_t)z * sA;
    Bm += (size_t)z * sB;
    C  += (size_t)z * sC;
    const float* Rp = RES ? (res + (size_t)z * sC) : nullptr;

    const int row0 = blockIdx.y * BM;
    const int col0 = blockIdx.x * BN;
    const int tid  = threadIdx.x;

    // A-tile load mapping: 128 rows x 8 cols, one float4 per thread
    const int aRow = tid >> 1;
    const int aCol = (tid & 1) << 2;
    // B-tile load mapping
    int bRow, bCol;
    if (BT) { bRow = tid >> 1; bCol = (tid & 1) << 2; }   // n = bRow, k = bCol
    else    { bRow = tid >> 5; bCol = (tid & 31) << 2; }  // k = bRow, n = bCol

    const int tRow = (tid >> 4) * TM;
    const int tCol = (tid & 15) * TN;

    float acc[TM][TN];
#pragma unroll
    for (int i = 0; i < TM; i++)
#pragma unroll
        for (int j = 0; j < TN; j++) acc[i][j] = 0.0f;

    const float* Aptr = A + (size_t)row0 * lda;

    for (int k0 = 0; k0 < K; k0 += BK) {
        // --- stage A tile (transposed into As) ---
        {
            float4 a4 = *(const float4*)(Aptr + (size_t)aRow * lda + k0 + aCol);
            As[(aCol + 0) * BM + aRow] = a4.x;
            As[(aCol + 1) * BM + aRow] = a4.y;
            As[(aCol + 2) * BM + aRow] = a4.z;
            As[(aCol + 3) * BM + aRow] = a4.w;
        }
        // --- stage B tile ---
        if (BT) {
            float4 b4 = *(const float4*)(Bm + (size_t)(col0 + bRow) * ldb + k0 + bCol);
            Bs[(bCol + 0) * BN + bRow] = b4.x;
            Bs[(bCol + 1) * BN + bRow] = b4.y;
            Bs[(bCol + 2) * BN + bRow] = b4.z;
            Bs[(bCol + 3) * BN + bRow] = b4.w;
        } else {
            float4 b4 = *(const float4*)(Bm + (size_t)(k0 + bRow) * ldb + col0 + bCol);
            *(float4*)(&Bs[bRow * BN + bCol]) = b4;
        }
        __syncthreads();

#pragma unroll
        for (int kk = 0; kk < BK; kk++) {
            float regM[TM], regN[TN];
            *(float4*)(regM)     = *(const float4*)(&As[kk * BM + tRow]);
            *(float4*)(regM + 4) = *(const float4*)(&As[kk * BM + tRow + 4]);
            *(float4*)(regN)     = *(const float4*)(&Bs[kk * BN + tCol]);
            *(float4*)(regN + 4) = *(const float4*)(&Bs[kk * BN + tCol + 4]);
#pragma unroll
            for (int i = 0; i < TM; i++)
#pragma unroll
                for (int j = 0; j < TN; j++)
                    acc[i][j] += regM[i] * regN[j];
        }
        __syncthreads();
    }

    // --- epilogue: alpha, +bias, +residual, relu, vectorized store ---
#pragma unroll
    for (int i = 0; i < TM; i++) {
        const size_t r = (size_t)(row0 + tRow + i);
#pragma unroll
        for (int jj = 0; jj < TN; jj += 4) {
            const int c = col0 + tCol + jj;
            float4 o;
            float* po = (float*)&o;
#pragma unroll
            for (int l = 0; l < 4; l++) {
                float v = acc[i][jj + l] * alpha;
                if (BIAS) v += bias[c + l];
                if (RES)  v += Rp[r * ldc + c + l];
                if (RELU) v = fmaxf(v, 0.0f);
                po[l] = v;
            }
            *(float4*)(C + r * ldc + c) = o;
        }
    }
}

// ---------------------------------------------------------------------------
// Row softmax over last dim (S_), mask added per (q,k); in place on scores.
// One block (256 thr) per row; 8 elements per thread.
// ---------------------------------------------------------------------------
__global__ __launch_bounds__(256) void softmax_k(float* __restrict__ s,
                                                 const float* __restrict__ mask)
{
    const int row = blockIdx.x;            // 0 .. B*S-1
    const int q   = row & (S_ - 1);        // row within batch
    float* p = s + (size_t)row * S_;
    const float* mrow = mask + (size_t)q * S_;
    const int tid = threadIdx.x;

    __shared__ float red[256];

    float vals[8];
    float vmax = -3.0e38f;
#pragma unroll
    for (int i = 0; i < 8; i++) {
        const int idx = tid + i * 256;
        const float v = p[idx] + mrow[idx];
        vals[i] = v;
        vmax = fmaxf(vmax, v);
    }
    red[tid] = vmax;
    __syncthreads();
    for (int o = 128; o > 0; o >>= 1) {
        if (tid < o) red[tid] = fmaxf(red[tid], red[tid + o]);
        __syncthreads();
    }
    vmax = red[0];
    __syncthreads();

    float sum = 0.0f;
#pragma unroll
    for (int i = 0; i < 8; i++) {
        const float e = __expf(vals[i] - vmax);
        vals[i] = e;
        sum += e;
    }
    red[tid] = sum;
    __syncthreads();
    for (int o = 128; o > 0; o >>= 1) {
        if (tid < o) red[tid] += red[tid + o];
        __syncthreads();
    }
    const float inv = 1.0f / red[0];
#pragma unroll
    for (int i = 0; i < 8; i++)
        p[tid + i * 256] = vals[i] * inv;
}

// ---------------------------------------------------------------------------
// LayerNorm over last dim (H_=1024): one block (256 thr) per row, float4.
// ---------------------------------------------------------------------------
__global__ __launch_bounds__(256) void ln_k(const float* __restrict__ y,
                                            const float* __restrict__ gamma,
                                            const float* __restrict__ beta,
                                            float* __restrict__ out)
{
    const int row = blockIdx.x;
    const float4* p4 = (const float4*)(y + (size_t)row * H_);
    const int tid = threadIdx.x;

    __shared__ float rs[256];
    __shared__ float rq[256];

    const float4 v = p4[tid];
    float s  = v.x + v.y + v.z + v.w;
    float sq = v.x * v.x + v.y * v.y + v.z * v.z + v.w * v.w;
    rs[tid] = s; rq[tid] = sq;
    __syncthreads();
    for (int o = 128; o > 0; o >>= 1) {
        if (tid < o) { rs[tid] += rs[tid + o]; rq[tid] += rq[tid + o]; }
        __syncthreads();
    }
    const float mu  = rs[0] * (1.0f / H_);
    const float var = rq[0] * (1.0f / H_) - mu * mu;
    const float inv = rsqrtf(var + 1e-5f);

    const float4 g = ((const float4*)gamma)[tid];
    const float4 b = ((const float4*)beta)[tid];
    float4 o;
    o.x = (v.x - mu) * inv * g.x + b.x;
    o.y = (v.y - mu) * inv * g.y + b.y;
    o.z = (v.z - mu) * inv * g.z + b.z;
    o.w = (v.w - mu) * inv * g.w + b.w;
    ((float4*)(out + (size_t)row * H_))[tid] = o;
}

// ---------------------------------------------------------------------------
// Launch
// ---------------------------------------------------------------------------
extern "C" void kernel_launch(void* const* d_in, const int* in_sizes, int n_in,
                              void* d_out, int out_size)
{
    const float* x     = (const float*)d_in[0];
    const float* mask  = (const float*)d_in[1];
    const float* qW    = (const float*)d_in[2];
    const float* qb    = (const float*)d_in[3];
    const float* kW    = (const float*)d_in[4];
    const float* kb    = (const float*)d_in[5];
    const float* vW    = (const float*)d_in[6];
    const float* vb    = (const float*)d_in[7];
    const float* w1    = (const float*)d_in[8];
    const float* b1    = (const float*)d_in[9];
    const float* w2    = (const float*)d_in[10];
    const float* b2    = (const float*)d_in[11];
    const float* gamma = (const float*)d_in[12];
    const float* beta  = (const float*)d_in[13];
    float* out = (float*)d_out;

    float *qp, *kp, *vp, *sp, *ap, *hp, *yp;
    cudaGetSymbolAddress((void**)&qp, g_q);
    cudaGetSymbolAddress((void**)&kp, g_k);
    cudaGetSymbolAddress((void**)&vp, g_v);
    cudaGetSymbolAddress((void**)&sp, g_s);
    cudaGetSymbolAddress((void**)&ap, g_attn);
    cudaGetSymbolAddress((void**)&hp, g_h);
    cudaGetSymbolAddress((void**)&yp, g_y);

    const dim3 blk(256);

    // --- QKV projections: [8192,1024] = x @ W + b ---
    {
        dim3 g(H_ / 128, NTOK / 128, 1);
        gemm_k<false, true, false, false><<<g, blk>>>(x, qW, qb, nullptr, qp,
            NTOK, H_, H_, H_, H_, H_, 0, 0, 0, 1.0f);
        gemm_k<false, true, false, false><<<g, blk>>>(x, kW, kb, nullptr, kp,
            NTOK, H_, H_, H_, H_, H_, 0, 0, 0, 1.0f);
        gemm_k<false, true, false, false><<<g, blk>>>(x, vW, vb, nullptr, vp,
            NTOK, H_, H_, H_, H_, H_, 0, 0, 0, 1.0f);
    }

    // --- scores: per batch, S = (q @ k^T) / sqrt(H) ---
    {
        dim3 g(S_ / 128, S_ / 128, B_);
        gemm_k<true, false, false, false><<<g, blk>>>(qp, kp, nullptr, nullptr, sp,
            S_, S_, H_, H_, H_, S_,
            (size_t)S_ * H_, (size_t)S_ * H_, (size_t)S_ * S_, 0.03125f /* 1/sqrt(1024) */);
    }

    // --- softmax(scores + mask), in place ---
    softmax_k<<<NTOK, blk>>>(sp, mask);

    // --- attn = a @ v : per batch [S,S] x [S,H] ---
    {
        dim3 g(H_ / 128, S_ / 128, B_);
        gemm_k<false, false, false, false><<<g, blk>>>(sp, vp, nullptr, nullptr, ap,
            S_, H_, S_, S_, H_, H_,
            (size_t)S_ * S_, (size_t)S_ * H_, (size_t)S_ * H_, 1.0f);
    }

    // --- FFN1: h = relu(attn @ w1 + b1) : [8192,4096] ---
    {
        dim3 g(F_ / 128, NTOK / 128, 1);
        gemm_k<false, true, true, false><<<g, blk>>>(ap, w1, b1, nullptr, hp,
            NTOK, F_, H_, H_, F_, F_, 0, 0, 0, 1.0f);
    }

    // --- FFN2 + residual: y = attn + h @ w2 + b2 : [8192,1024] ---
    {
        dim3 g(H_ / 128, NTOK / 128, 1);
        gemm_k<false, true, false, true><<<g, blk>>>(hp, w2, b2, ap, yp,
            NTOK, H_, F_, F_, H_, H_, 0, 0, 0, 1.0f);
    }

    // --- LayerNorm -> out ---
    ln_k<<<NTOK, blk>>>(yp, gamma, beta, out);
}

// round 3
// speedup vs baseline: 2.2126x; 2.2126x over previous
#include <cuda_runtime.h>
#include <cstdint>
#include <math.h>

#define B_   4
#define S_   2048
#define H_   1024
#define F_   4096
#define NTOK (B_ * S_)   // 8192

// ---------------------------------------------------------------------------
// Scratch (static device globals)
// ---------------------------------------------------------------------------
__device__ float g_q[(size_t)NTOK * H_];
__device__ float g_k[(size_t)NTOK * H_];
__device__ float g_v[(size_t)NTOK * H_];
__device__ float g_s[(size_t)B_ * S_ * S_];
__device__ float g_attn[(size_t)NTOK * H_];
__device__ float g_h[(size_t)NTOK * F_];
__device__ float g_y[(size_t)NTOK * H_];
__device__ float g_wqt[(size_t)H_ * H_];
__device__ float g_wkt[(size_t)H_ * H_];
__device__ float g_wvt[(size_t)H_ * H_];
__device__ float g_w1t[(size_t)H_ * F_];
__device__ float g_w2t[(size_t)F_ * H_];
__device__ float g_vt[(size_t)NTOK * H_];

// ---------------------------------------------------------------------------
// Helpers
// ---------------------------------------------------------------------------
__device__ __forceinline__ uint32_t f2tf(float f) {
    uint32_t r;
    asm("cvt.rna.tf32.f32 %0, %1;" : "=r"(r) : "f"(f));
    return r;
}

__device__ __forceinline__ void mma8(float c[4], const uint32_t a[4], const uint32_t b[2]) {
    asm volatile("mma.sync.aligned.m16n8k8.row.col.f32.tf32.tf32.f32 "
                 "{%0,%1,%2,%3}, {%4,%5,%6,%7}, {%8,%9}, {%0,%1,%2,%3};"
                 : "+f"(c[0]), "+f"(c[1]), "+f"(c[2]), "+f"(c[3])
                 : "r"(a[0]), "r"(a[1]), "r"(a[2]), "r"(a[3]), "r"(b[0]), "r"(b[1]));
}

// ---------------------------------------------------------------------------
// TF32 tensor-core GEMM via mma.sync:
//   C = alpha * A[M,K] * Bw[N,K]^T (+bias) (+res) (relu)
// Block tile 128x128, BK=16, 8 warps (2x4), warp tile 64x32.
// Smem: [128][20] u32 per operand per buffer, double buffered (40 KB static).
// M,N multiples of 128; K multiple of 16. Batched over blockIdx.z.
// ---------------------------------------------------------------------------
#define LDS_STRIDE 20

template <bool BIAS, bool RELU, bool RES>
__global__ __launch_bounds__(256) void tgemm(
    const float* __restrict__ A, const float* __restrict__ Bw,
    const float* __restrict__ bias, const float* __restrict__ res,
    float* __restrict__ C,
    int K, int lda, int ldb, int ldc,
    size_t sA, size_t sB, size_t sC, float alpha)
{
    __shared__ uint32_t smem[4 * 128 * LDS_STRIDE];   // A0,B0,A1,B1

    const int tid  = threadIdx.x;
    const int wid  = tid >> 5, lane = tid & 31;
    const int g    = lane >> 2, t4 = lane & 3;
    const int warpM = wid >> 2, warpN = wid & 3;

    const int z = blockIdx.z;
    A  += (size_t)z * sA;
    Bw += (size_t)z * sB;
    C  += (size_t)z * sC;
    const float* Rp = RES ? (res + (size_t)z * sC) : nullptr;

    const int n0 = blockIdx.x << 7, m0 = blockIdx.y << 7;
    const float* Ap = A  + (size_t)m0 * lda;
    const float* Bp = Bw + (size_t)n0 * ldb;

    const int srow = tid >> 1;
    const int scol = (tid & 1) << 3;

    float acc[4][4][4];
#pragma unroll
    for (int mt = 0; mt < 4; mt++)
#pragma unroll
        for (int nt = 0; nt < 4; nt++)
#pragma unroll
            for (int i = 0; i < 4; i++) acc[mt][nt][i] = 0.0f;

    float4 ldr[4];
    const int KT = K >> 4;

    // --- prologue: load k-tile 0, stage into buffer 0 ---
    {
        const float* a = Ap + (size_t)srow * lda + scol;
        ldr[0] = *(const float4*)a;
        ldr[1] = *(const float4*)(a + 4);
        const float* b = Bp + (size_t)srow * ldb + scol;
        ldr[2] = *(const float4*)b;
        ldr[3] = *(const float4*)(b + 4);
    }
    {
        uint32_t* da = smem + srow * LDS_STRIDE + scol;
        uint32_t* db = da + 128 * LDS_STRIDE;
        da[0] = f2tf(ldr[0].x); da[1] = f2tf(ldr[0].y); da[2] = f2tf(ldr[0].z); da[3] = f2tf(ldr[0].w);
        da[4] = f2tf(ldr[1].x); da[5] = f2tf(ldr[1].y); da[6] = f2tf(ldr[1].z); da[7] = f2tf(ldr[1].w);
        db[0] = f2tf(ldr[2].x); db[1] = f2tf(ldr[2].y); db[2] = f2tf(ldr[2].z); db[3] = f2tf(ldr[2].w);
        db[4] = f2tf(ldr[3].x); db[5] = f2tf(ldr[3].y); db[6] = f2tf(ldr[3].z); db[7] = f2tf(ldr[3].w);
    }

    for (int kt = 0; kt < KT; kt++) {
        __syncthreads();
        const int buf = kt & 1;
        const bool hasNext = (kt + 1 < KT);

        if (hasNext) {
            const float* a = Ap + (size_t)srow * lda + ((kt + 1) << 4) + scol;
            ldr[0] = *(const float4*)a;
            ldr[1] = *(const float4*)(a + 4);
            const float* b = Bp + (size_t)srow * ldb + ((kt + 1) << 4) + scol;
            ldr[2] = *(const float4*)b;
            ldr[3] = *(const float4*)(b + 4);
        }

        const uint32_t* As = smem + buf * (2 * 128 * LDS_STRIDE);
        const uint32_t* Bs = As + 128 * LDS_STRIDE;

#pragma unroll
        for (int ks = 0; ks < 2; ks++) {
            uint32_t afr[4][4], bfr[4][2];
#pragma unroll
            for (int mt = 0; mt < 4; mt++) {
                const uint32_t* p = As + (warpM * 64 + mt * 16 + g) * LDS_STRIDE + ks * 8 + t4;
                afr[mt][0] = p[0];
                afr[mt][1] = p[8 * LDS_STRIDE];
                afr[mt][2] = p[4];
                afr[mt][3] = p[8 * LDS_STRIDE + 4];
            }
#pragma unroll
            for (int nt = 0; nt < 4; nt++) {
                const uint32_t* p = Bs + (warpN * 32 + nt * 8 + g) * LDS_STRIDE + ks * 8 + t4;
                bfr[nt][0] = p[0];
                bfr[nt][1] = p[4];
            }
#pragma unroll
            for (int mt = 0; mt < 4; mt++)
#pragma unroll
                for (int nt = 0; nt < 4; nt++)
                    mma8(acc[mt][nt], afr[mt], bfr[nt]);
        }

        if (hasNext) {
            uint32_t* da = smem + (buf ^ 1) * (2 * 128 * LDS_STRIDE) + srow * LDS_STRIDE + scol;
            uint32_t* db = da + 128 * LDS_STRIDE;
            da[0] = f2tf(ldr[0].x); da[1] = f2tf(ldr[0].y); da[2] = f2tf(ldr[0].z); da[3] = f2tf(ldr[0].w);
            da[4] = f2tf(ldr[1].x); da[5] = f2tf(ldr[1].y); da[6] = f2tf(ldr[1].z); da[7] = f2tf(ldr[1].w);
            db[0] = f2tf(ldr[2].x); db[1] = f2tf(ldr[2].y); db[2] = f2tf(ldr[2].z); db[3] = f2tf(ldr[2].w);
            db[4] = f2tf(ldr[3].x); db[5] = f2tf(ldr[3].y); db[6] = f2tf(ldr[3].z); db[7] = f2tf(ldr[3].w);
        }
    }

    // --- fused epilogue, direct float2 stores ---
    const int rbase = m0 + warpM * 64;
    const int cbase = n0 + warpN * 32;
#pragma unroll
    for (int mt = 0; mt < 4; mt++) {
#pragma unroll
        for (int nt = 0; nt < 4; nt++) {
            const int col = cbase + nt * 8 + (t4 << 1);
            float bx = 0.f, by = 0.f;
            if (BIAS) {
                float2 bb = *(const float2*)(bias + col);
                bx = bb.x; by = bb.y;
            }
#pragma unroll
            for (int hh = 0; hh < 2; hh++) {
                const int row = rbase + mt * 16 + g + hh * 8;
                float v0 = acc[mt][nt][hh * 2 + 0] * alpha;
                float v1 = acc[mt][nt][hh * 2 + 1] * alpha;
                if (BIAS) { v0 += bx; v1 += by; }
                if (RES) {
                    float2 rr = *(const float2*)(Rp + (size_t)row * ldc + col);
                    v0 += rr.x; v1 += rr.y;
                }
                if (RELU) { v0 = fmaxf(v0, 0.f); v1 = fmaxf(v1, 0.f); }
                float2 o; o.x = v0; o.y = v1;
                *(float2*)(C + (size_t)row * ldc + col) = o;
            }
        }
    }
}

// ---------------------------------------------------------------------------
// Transpose: src [R,C] -> dst [C,R], batched over z. R,C multiples of 32.
// ---------------------------------------------------------------------------
__global__ __launch_bounds__(256) void transpose_k(const float* __restrict__ src,
                                                   float* __restrict__ dst, int R, int C)
{
    __shared__ float t[32][33];
    const size_t zoff = (size_t)blockIdx.z * R * C;
    src += zoff; dst += zoff;
    const int bx = blockIdx.x << 5, by = blockIdx.y << 5;
    const int tx = threadIdx.x & 31, ty = (threadIdx.x >> 5) << 2;
#pragma unroll
    for (int j = 0; j < 4; j++)
        t[ty + j][tx] = src[(size_t)(by + ty + j) * C + bx + tx];
    __syncthreads();
#pragma unroll
    for (int j = 0; j < 4; j++)
        dst[(size_t)(bx + ty + j) * R + by + tx] = t[tx][ty + j];
}

// ---------------------------------------------------------------------------
// Row softmax (S_ wide) with mask
// ---------------------------------------------------------------------------
__global__ __launch_bounds__(256) void softmax_k(float* __restrict__ s,
                                                 const float* __restrict__ mask)
{
    const int row = blockIdx.x;
    const int q   = row & (S_ - 1);
    float* p = s + (size_t)row * S_;
    const float* mrow = mask + (size_t)q * S_;
    const int tid = threadIdx.x;
    __shared__ float red[256];

    float vals[8];
    float vmax = -3.0e38f;
#pragma unroll
    for (int i = 0; i < 8; i++) {
        const int idx = tid + i * 256;
        const float v = p[idx] + mrow[idx];
        vals[i] = v;
        vmax = fmaxf(vmax, v);
    }
    red[tid] = vmax; __syncthreads();
    for (int o = 128; o > 0; o >>= 1) {
        if (tid < o) red[tid] = fmaxf(red[tid], red[tid + o]);
        __syncthreads();
    }
    vmax = red[0]; __syncthreads();
    float sum = 0.0f;
#pragma unroll
    for (int i = 0; i < 8; i++) { const float e = __expf(vals[i] - vmax); vals[i] = e; sum += e; }
    red[tid] = sum; __syncthreads();
    for (int o = 128; o > 0; o >>= 1) {
        if (tid < o) red[tid] += red[tid + o];
        __syncthreads();
    }
    const float inv = 1.0f / red[0];
#pragma unroll
    for (int i = 0; i < 8; i++) p[tid + i * 256] = vals[i] * inv;
}

// ---------------------------------------------------------------------------
// LayerNorm (H_=1024)
// ---------------------------------------------------------------------------
__global__ __launch_bounds__(256) void ln_k(const float* __restrict__ y,
                                            const float* __restrict__ gamma,
                                            const float* __restrict__ beta,
                                            float* __restrict__ out)
{
    const int row = blockIdx.x;
    const float4* p4 = (const float4*)(y + (size_t)row * H_);
    const int tid = threadIdx.x;
    __shared__ float rs[256], rq[256];

    const float4 v = p4[tid];
    rs[tid] = v.x + v.y + v.z + v.w;
    rq[tid] = v.x * v.x + v.y * v.y + v.z * v.z + v.w * v.w;
    __syncthreads();
    for (int o = 128; o > 0; o >>= 1) {
        if (tid < o) { rs[tid] += rs[tid + o]; rq[tid] += rq[tid + o]; }
        __syncthreads();
    }
    const float mu  = rs[0] * (1.0f / H_);
    const float var = rq[0] * (1.0f / H_) - mu * mu;
    const float inv = rsqrtf(var + 1e-5f);
    const float4 g = ((const float4*)gamma)[tid];
    const float4 b = ((const float4*)beta)[tid];
    float4 o;
    o.x = (v.x - mu) * inv * g.x + b.x;
    o.y = (v.y - mu) * inv * g.y + b.y;
    o.z = (v.z - mu) * inv * g.z + b.z;
    o.w = (v.w - mu) * inv * g.w + b.w;
    ((float4*)(out + (size_t)row * H_))[tid] = o;
}

// ---------------------------------------------------------------------------
// Launch
// ---------------------------------------------------------------------------
extern "C" void kernel_launch(void* const* d_in, const int* in_sizes, int n_in,
                              void* d_out, int out_size)
{
    const float* x     = (const float*)d_in[0];
    const float* mask  = (const float*)d_in[1];
    const float* qW    = (const float*)d_in[2];
    const float* qb    = (const float*)d_in[3];
    const float* kW    = (const float*)d_in[4];
    const float* kb    = (const float*)d_in[5];
    const float* vW    = (const float*)d_in[6];
    const float* vb    = (const float*)d_in[7];
    const float* w1    = (const float*)d_in[8];
    const float* b1    = (const float*)d_in[9];
    const float* w2    = (const float*)d_in[10];
    const float* b2    = (const float*)d_in[11];
    const float* gamma = (const float*)d_in[12];
    const float* beta  = (const float*)d_in[13];
    float* out = (float*)d_out;

    float *qp, *kp, *vp, *sp, *ap, *hp, *yp;
    float *wqt, *wkt, *wvt, *w1t, *w2t, *vt;
    cudaGetSymbolAddress((void**)&qp, g_q);
    cudaGetSymbolAddress((void**)&kp, g_k);
    cudaGetSymbolAddress((void**)&vp, g_v);
    cudaGetSymbolAddress((void**)&sp, g_s);
    cudaGetSymbolAddress((void**)&ap, g_attn);
    cudaGetSymbolAddress((void**)&hp, g_h);
    cudaGetSymbolAddress((void**)&yp, g_y);
    cudaGetSymbolAddress((void**)&wqt, g_wqt);
    cudaGetSymbolAddress((void**)&wkt, g_wkt);
    cudaGetSymbolAddress((void**)&wvt, g_wvt);
    cudaGetSymbolAddress((void**)&w1t, g_w1t);
    cudaGetSymbolAddress((void**)&w2t, g_w2t);
    cudaGetSymbolAddress((void**)&vt, g_vt);

    const dim3 blk(256);

    // --- transpose weights to [N,K] ---
    transpose_k<<<dim3(H_ / 32, H_ / 32, 1), blk>>>(qW, wqt, H_, H_);
    transpose_k<<<dim3(H_ / 32, H_ / 32, 1), blk>>>(kW, wkt, H_, H_);
    transpose_k<<<dim3(H_ / 32, H_ / 32, 1), blk>>>(vW, wvt, H_, H_);
    transpose_k<<<dim3(F_ / 32, H_ / 32, 1), blk>>>(w1, w1t, H_, F_);
    transpose_k<<<dim3(H_ / 32, F_ / 32, 1), blk>>>(w2, w2t, F_, H_);

    // --- QKV projections ---
    {
        dim3 g(H_ / 128, NTOK / 128, 1);
        tgemm<true, false, false><<<g, blk>>>(x, wqt, qb, nullptr, qp,
            H_, H_, H_, H_, 0, 0, 0, 1.0f);
        tgemm<true, false, false><<<g, blk>>>(x, wkt, kb, nullptr, kp,
            H_, H_, H_, H_, 0, 0, 0, 1.0f);
        tgemm<true, false, false><<<g, blk>>>(x, wvt, vb, nullptr, vp,
            H_, H_, H_, H_, 0, 0, 0, 1.0f);
    }

    // --- scores: per batch S = q @ k^T / sqrt(H) ---
    {
        dim3 g(S_ / 128, S_ / 128, B_);
        tgemm<false, false, false><<<g, blk>>>(qp, kp, nullptr, nullptr, sp,
            H_, H_, H_, S_,
            (size_t)S_ * H_, (size_t)S_ * H_, (size_t)S_ * S_, 0.03125f);
    }

    // --- softmax ---
    softmax_k<<<NTOK, blk>>>(sp, mask);

    // --- V^T per batch ---
    transpose_k<<<dim3(H_ / 32, S_ / 32, B_), blk>>>(vp, vt, S_, H_);

    // --- attn = a @ v (B operand = V^T [H,S]) ---
    {
        dim3 g(H_ / 128, S_ / 128, B_);
        tgemm<false, false, false><<<g, blk>>>(sp, vt, nullptr, nullptr, ap,
            S_, S_, S_, H_,
            (size_t)S_ * S_, (size_t)S_ * H_, (size_t)S_ * H_, 1.0f);
    }

    // --- FFN1: h = relu(attn @ w1 + b1) ---
    {
        dim3 g(F_ / 128, NTOK / 128, 1);
        tgemm<true, true, false><<<g, blk>>>(ap, w1t, b1, nullptr, hp,
            H_, H_, H_, F_, 0, 0, 0, 1.0f);
    }

    // --- FFN2 + residual ---
    {
        dim3 g(H_ / 128, NTOK / 128, 1);
        tgemm<true, false, true><<<g, blk>>>(hp, w2t, b2, ap, yp,
            F_, F_, F_, H_, 0, 0, 0, 1.0f);
    }

    // --- LayerNorm ---
    ln_k<<<NTOK, blk>>>(yp, gamma, beta, out);
}

// round 4
// speedup vs baseline: 3.0583x; 1.3822x over previous
#include <cuda_runtime.h>
#include <cstdint>
#include <math.h>

#define B_   4
#define S_   2048
#define H_   1024
#define F_   4096
#define NTOK (B_ * S_)   // 8192

// ---------------------------------------------------------------------------
// Scratch (static device globals)
// ---------------------------------------------------------------------------
__device__ float g_xr[(size_t)NTOK * H_];
__device__ float g_q[(size_t)NTOK * H_];
__device__ float g_k[(size_t)NTOK * H_];
__device__ float g_v[(size_t)NTOK * H_];
__device__ float g_s[(size_t)B_ * S_ * S_];
__device__ float g_attn[(size_t)NTOK * H_];
__device__ float g_h[(size_t)NTOK * F_];
__device__ float g_y[(size_t)NTOK * H_];
__device__ float g_wqt[(size_t)H_ * H_];
__device__ float g_wkt[(size_t)H_ * H_];
__device__ float g_wvt[(size_t)H_ * H_];
__device__ float g_w1t[(size_t)H_ * F_];
__device__ float g_w2t[(size_t)F_ * H_];
__device__ float g_vt[(size_t)NTOK * H_];

// ---------------------------------------------------------------------------
// Helpers
// ---------------------------------------------------------------------------
__device__ __forceinline__ uint32_t f2tf(float f) {
    uint32_t r;
    asm("cvt.rna.tf32.f32 %0, %1;" : "=r"(r) : "f"(f));
    return r;
}
__device__ __forceinline__ float f2tff(float f) {
    return __uint_as_float(f2tf(f));
}
__device__ __forceinline__ uint32_t smem_u32(const void* p) {
    uint32_t a;
    asm("{ .reg .u64 t; cvta.to.shared.u64 t, %1; cvt.u32.u64 %0, t; }" : "=r"(a) : "l"(p));
    return a;
}
__device__ __forceinline__ void cp16(uint32_t s, const void* g) {
    asm volatile("cp.async.cg.shared.global [%0], [%1], 16;" :: "r"(s), "l"(g) : "memory");
}
#define CP_COMMIT() asm volatile("cp.async.commit_group;" ::: "memory")
#define CP_WAIT1()  asm volatile("cp.async.wait_group 1;" ::: "memory")

__device__ __forceinline__ void mma8(float c[4], const uint32_t a[4], const uint32_t b[2]) {
    asm volatile("mma.sync.aligned.m16n8k8.row.col.f32.tf32.tf32.f32 "
                 "{%0,%1,%2,%3}, {%4,%5,%6,%7}, {%8,%9}, {%0,%1,%2,%3};"
                 : "+f"(c[0]), "+f"(c[1]), "+f"(c[2]), "+f"(c[3])
                 : "r"(a[0]), "r"(a[1]), "r"(a[2]), "r"(a[3]), "r"(b[0]), "r"(b[1]));
}

// ---------------------------------------------------------------------------
// TF32 tensor-core GEMM, cp.async 3-stage pipeline:
//   C = alpha * A[M,K] * Bw[N,K]^T (+bias) (+res) (relu) (round-to-tf32 store)
// CTA tile 128x256, BK=16, 8 warps (2x4), warp tile 64x64.
// All GEMM inputs must already be tf32-rounded in gmem (cp.async copies raw).
// M mult of 128, N mult of 256, K mult of 16. Batched over blockIdx.z.
// Smem per stage: A 128x20 u32 + B 256x20 u32 = 30720 B; 3 stages = 92160 B.
// ---------------------------------------------------------------------------
#define LDSS 20
#define STAGE_U32 (128 * LDSS + 256 * LDSS)     // 7680
#define STAGE_B   (STAGE_U32 * 4)               // 30720
#define SMEM_B    (3 * STAGE_B)                 // 92160

template <bool BIAS, bool RELU, bool RES, bool ROUND>
__global__ __launch_bounds__(256, 1) void tgemm(
    const float* __restrict__ A, const float* __restrict__ Bw,
    const float* __restrict__ bias, const float* __restrict__ res,
    float* __restrict__ C,
    int K, int lda, int ldb, int ldc,
    size_t sA, size_t sB, size_t sC, float alpha)
{
    extern __shared__ uint32_t smem[];
    const uint32_t sbase = smem_u32(smem);

    const int tid  = threadIdx.x;
    const int wid  = tid >> 5, lane = tid & 31;
    const int g    = lane >> 2, t4 = lane & 3;
    const int warpM = wid >> 2, warpN = wid & 3;

    const int z = blockIdx.z;
    A  += (size_t)z * sA;
    Bw += (size_t)z * sB;
    C  += (size_t)z * sC;
    const float* Rp = RES ? (res + (size_t)z * sC) : nullptr;

    const int n0 = blockIdx.x << 8, m0 = blockIdx.y << 7;
    const float* Ap = A  + (size_t)m0 * lda;
    const float* Bp = Bw + (size_t)n0 * ldb;

    // cp.async chunk mapping (16B chunks; rows of 16 u32 + 4 pad)
    const int aRow = tid >> 2,          aC4 = (tid & 3) << 2;   // chunks tid, tid+256... wait below
    // A: 512 chunks -> 2 per thread; B: 1024 chunks -> 4 per thread
    // chunk c: row = c>>2, col4 = (c&3)*4

    const int KT = K >> 4;

    auto issue = [&](int kt) {
        const uint32_t s = sbase + (uint32_t)(kt % 3) * STAGE_B;
        const int kb = kt << 4;
#pragma unroll
        for (int j = 0; j < 2; j++) {
            const int c = tid + (j << 8);
            const int row = c >> 2, c4 = (c & 3) << 2;
            cp16(s + (uint32_t)((row * LDSS + c4) << 2),
                 Ap + (size_t)row * lda + kb + c4);
        }
        const uint32_t sB2 = s + (uint32_t)(128 * LDSS * 4);
#pragma unroll
        for (int j = 0; j < 4; j++) {
            const int c = tid + (j << 8);
            const int row = c >> 2, c4 = (c & 3) << 2;
            cp16(sB2 + (uint32_t)((row * LDSS + c4) << 2),
                 Bp + (size_t)row * ldb + kb + c4);
        }
    };

    (void)aRow; (void)aC4;

    float acc[4][8][4];
#pragma unroll
    for (int mt = 0; mt < 4; mt++)
#pragma unroll
        for (int nt = 0; nt < 8; nt++)
#pragma unroll
            for (int i = 0; i < 4; i++) acc[mt][nt][i] = 0.0f;

    // prologue: stages 0,1
    issue(0); CP_COMMIT();
    if (KT > 1) issue(1);
    CP_COMMIT();

    for (int kt = 0; kt < KT; kt++) {
        CP_WAIT1();
        __syncthreads();

        if (kt + 2 < KT) issue(kt + 2);
        CP_COMMIT();

        const uint32_t* As = smem + (kt % 3) * STAGE_U32;
        const uint32_t* Bs = As + 128 * LDSS;

#pragma unroll
        for (int ks = 0; ks < 2; ks++) {
            uint32_t afr[4][4], bfr[8][2];
#pragma unroll
            for (int mt = 0; mt < 4; mt++) {
                const uint32_t* p = As + (warpM * 64 + mt * 16 + g) * LDSS + ks * 8 + t4;
                afr[mt][0] = p[0];
                afr[mt][1] = p[8 * LDSS];
                afr[mt][2] = p[4];
                afr[mt][3] = p[8 * LDSS + 4];
            }
#pragma unroll
            for (int nt = 0; nt < 8; nt++) {
                const uint32_t* p = Bs + (warpN * 64 + nt * 8 + g) * LDSS + ks * 8 + t4;
                bfr[nt][0] = p[0];
                bfr[nt][1] = p[4];
            }
#pragma unroll
            for (int mt = 0; mt < 4; mt++)
#pragma unroll
                for (int nt = 0; nt < 8; nt++)
                    mma8(acc[mt][nt], afr[mt], bfr[nt]);
        }
        __syncthreads();
    }

    // --- fused epilogue, direct float2 stores ---
    const int rbase = m0 + warpM * 64;
    const int cbase = n0 + warpN * 64;
#pragma unroll
    for (int mt = 0; mt < 4; mt++) {
#pragma unroll
        for (int nt = 0; nt < 8; nt++) {
            const int col = cbase + nt * 8 + (t4 << 1);
            float bx = 0.f, by = 0.f;
            if (BIAS) {
                float2 bb = *(const float2*)(bias + col);
                bx = bb.x; by = bb.y;
            }
#pragma unroll
            for (int hh = 0; hh < 2; hh++) {
                const int row = rbase + mt * 16 + g + hh * 8;
                float v0 = acc[mt][nt][hh * 2 + 0] * alpha;
                float v1 = acc[mt][nt][hh * 2 + 1] * alpha;
                if (BIAS) { v0 += bx; v1 += by; }
                if (RES) {
                    float2 rr = *(const float2*)(Rp + (size_t)row * ldc + col);
                    v0 += rr.x; v1 += rr.y;
                }
                if (RELU) { v0 = fmaxf(v0, 0.f); v1 = fmaxf(v1, 0.f); }
                if (ROUND) { v0 = f2tff(v0); v1 = f2tff(v1); }
                float2 o; o.x = v0; o.y = v1;
                *(float2*)(C + (size_t)row * ldc + col) = o;
            }
        }
    }
}

// ---------------------------------------------------------------------------
// Elementwise tf32 round: out[i] = round_tf32(in[i])
// ---------------------------------------------------------------------------
__global__ __launch_bounds__(256) void round_k(const float* __restrict__ in,
                                               float* __restrict__ out)
{
    const size_t i = ((size_t)blockIdx.x * 256 + threadIdx.x) * 4;
    float4 v = *(const float4*)(in + i);
    v.x = f2tff(v.x); v.y = f2tff(v.y); v.z = f2tff(v.z); v.w = f2tff(v.w);
    *(float4*)(out + i) = v;
}

// ---------------------------------------------------------------------------
// Transpose + tf32 round: src [R,C] -> dst [C,R], batched over z.
// ---------------------------------------------------------------------------
__global__ __launch_bounds__(256) void transpose_k(const float* __restrict__ src,
                                                   float* __restrict__ dst, int R, int C)
{
    __shared__ float t[32][33];
    const size_t zoff = (size_t)blockIdx.z * R * C;
    src += zoff; dst += zoff;
    const int bx = blockIdx.x << 5, by = blockIdx.y << 5;
    const int tx = threadIdx.x & 31, ty = (threadIdx.x >> 5) << 2;
#pragma unroll
    for (int j = 0; j < 4; j++)
        t[ty + j][tx] = src[(size_t)(by + ty + j) * C + bx + tx];
    __syncthreads();
#pragma unroll
    for (int j = 0; j < 4; j++)
        dst[(size_t)(bx + ty + j) * R + by + tx] = f2tff(t[tx][ty + j]);
}

// ---------------------------------------------------------------------------
// Row softmax (S_ wide) with mask; output rounded to tf32
// ---------------------------------------------------------------------------
__global__ __launch_bounds__(256) void softmax_k(float* __restrict__ s,
                                                 const float* __restrict__ mask)
{
    const int row = blockIdx.x;
    const int q   = row & (S_ - 1);
    float* p = s + (size_t)row * S_;
    const float* mrow = mask + (size_t)q * S_;
    const int tid = threadIdx.x;
    __shared__ float red[256];

    float vals[8];
    float vmax = -3.0e38f;
#pragma unroll
    for (int i = 0; i < 8; i++) {
        const int idx = tid + i * 256;
        const float v = p[idx] + mrow[idx];
        vals[i] = v;
        vmax = fmaxf(vmax, v);
    }
    red[tid] = vmax; __syncthreads();
    for (int o = 128; o > 0; o >>= 1) {
        if (tid < o) red[tid] = fmaxf(red[tid], red[tid + o]);
        __syncthreads();
    }
    vmax = red[0]; __syncthreads();
    float sum = 0.0f;
#pragma unroll
    for (int i = 0; i < 8; i++) { const float e = __expf(vals[i] - vmax); vals[i] = e; sum += e; }
    red[tid] = sum; __syncthreads();
    for (int o = 128; o > 0; o >>= 1) {
        if (tid < o) red[tid] += red[tid + o];
        __syncthreads();
    }
    const float inv = 1.0f / red[0];
#pragma unroll
    for (int i = 0; i < 8; i++) p[tid + i * 256] = f2tff(vals[i] * inv);
}

// ---------------------------------------------------------------------------
// LayerNorm (H_=1024)
// ---------------------------------------------------------------------------
__global__ __launch_bounds__(256) void ln_k(const float* __restrict__ y,
                                            const float* __restrict__ gamma,
                                            const float* __restrict__ beta,
                                            float* __restrict__ out)
{
    const int row = blockIdx.x;
    const float4* p4 = (const float4*)(y + (size_t)row * H_);
    const int tid = threadIdx.x;
    __shared__ float rs[256], rq[256];

    const float4 v = p4[tid];
    rs[tid] = v.x + v.y + v.z + v.w;
    rq[tid] = v.x * v.x + v.y * v.y + v.z * v.z + v.w * v.w;
    __syncthreads();
    for (int o = 128; o > 0; o >>= 1) {
        if (tid < o) { rs[tid] += rs[tid + o]; rq[tid] += rq[tid + o]; }
        __syncthreads();
    }
    const float mu  = rs[0] * (1.0f / H_);
    const float var = rq[0] * (1.0f / H_) - mu * mu;
    const float inv = rsqrtf(var + 1e-5f);
    const float4 g = ((const float4*)gamma)[tid];
    const float4 b = ((const float4*)beta)[tid];
    float4 o;
    o.x = (v.x - mu) * inv * g.x + b.x;
    o.y = (v.y - mu) * inv * g.y + b.y;
    o.z = (v.z - mu) * inv * g.z + b.z;
    o.w = (v.w - mu) * inv * g.w + b.w;
    ((float4*)(out + (size_t)row * H_))[tid] = o;
}

// ---------------------------------------------------------------------------
// Launch
// ---------------------------------------------------------------------------
extern "C" void kernel_launch(void* const* d_in, const int* in_sizes, int n_in,
                              void* d_out, int out_size)
{
    const float* x     = (const float*)d_in[0];
    const float* mask  = (const float*)d_in[1];
    const float* qW    = (const float*)d_in[2];
    const float* qb    = (const float*)d_in[3];
    const float* kW    = (const float*)d_in[4];
    const float* kb    = (const float*)d_in[5];
    const float* vW    = (const float*)d_in[6];
    const float* vb    = (const float*)d_in[7];
    const float* w1    = (const float*)d_in[8];
    const float* b1    = (const float*)d_in[9];
    const float* w2    = (const float*)d_in[10];
    const float* b2    = (const float*)d_in[11];
    const float* gamma = (const float*)d_in[12];
    const float* beta  = (const float*)d_in[13];
    float* out = (float*)d_out;

    float *xr, *qp, *kp, *vp, *sp, *ap, *hp, *yp;
    float *wqt, *wkt, *wvt, *w1t, *w2t, *vt;
    cudaGetSymbolAddress((void**)&xr, g_xr);
    cudaGetSymbolAddress((void**)&qp, g_q);
    cudaGetSymbolAddress((void**)&kp, g_k);
    cudaGetSymbolAddress((void**)&vp, g_v);
    cudaGetSymbolAddress((void**)&sp, g_s);
    cudaGetSymbolAddress((void**)&ap, g_attn);
    cudaGetSymbolAddress((void**)&hp, g_h);
    cudaGetSymbolAddress((void**)&yp, g_y);
    cudaGetSymbolAddress((void**)&wqt, g_wqt);
    cudaGetSymbolAddress((void**)&wkt, g_wkt);
    cudaGetSymbolAddress((void**)&wvt, g_wvt);
    cudaGetSymbolAddress((void**)&w1t, g_w1t);
    cudaGetSymbolAddress((void**)&w2t, g_w2t);
    cudaGetSymbolAddress((void**)&vt, g_vt);

    cudaFuncSetAttribute((const void*)tgemm<true,  false, false, true >,
                         cudaFuncAttributeMaxDynamicSharedMemorySize, SMEM_B);
    cudaFuncSetAttribute((const void*)tgemm<true,  false, false, false>,
                         cudaFuncAttributeMaxDynamicSharedMemorySize, SMEM_B);
    cudaFuncSetAttribute((const void*)tgemm<false, false, false, false>,
                         cudaFuncAttributeMaxDynamicSharedMemorySize, SMEM_B);
    cudaFuncSetAttribute((const void*)tgemm<true,  true,  false, true >,
                         cudaFuncAttributeMaxDynamicSharedMemorySize, SMEM_B);
    cudaFuncSetAttribute((const void*)tgemm<true,  false, true,  false>,
                         cudaFuncAttributeMaxDynamicSharedMemorySize, SMEM_B);

    const dim3 blk(256);

    // --- pre-round x; transpose+round weights to [N,K] ---
    round_k<<<(NTOK * H_) / 1024, blk>>>(x, xr);
    transpose_k<<<dim3(H_ / 32, H_ / 32, 1), blk>>>(qW, wqt, H_, H_);
    transpose_k<<<dim3(H_ / 32, H_ / 32, 1), blk>>>(kW, wkt, H_, H_);
    transpose_k<<<dim3(H_ / 32, H_ / 32, 1), blk>>>(vW, wvt, H_, H_);
    transpose_k<<<dim3(F_ / 32, H_ / 32, 1), blk>>>(w1, w1t, H_, F_);
    transpose_k<<<dim3(H_ / 32, F_ / 32, 1), blk>>>(w2, w2t, F_, H_);

    // --- QKV projections (q,k stored tf32-rounded; v raw, rounded in vt) ---
    {
        dim3 g(H_ / 256, NTOK / 128, 1);
        tgemm<true, false, false, true ><<<g, blk, SMEM_B>>>(xr, wqt, qb, nullptr, qp,
            H_, H_, H_, H_, 0, 0, 0, 1.0f);
        tgemm<true, false, false, true ><<<g, blk, SMEM_B>>>(xr, wkt, kb, nullptr, kp,
            H_, H_, H_, H_, 0, 0, 0, 1.0f);
        tgemm<true, false, false, false><<<g, blk, SMEM_B>>>(xr, wvt, vb, nullptr, vp,
            H_, H_, H_, H_, 0, 0, 0, 1.0f);
    }

    // --- scores: per batch S = q @ k^T / sqrt(H) ---
    {
        dim3 g(S_ / 256, S_ / 128, B_);
        tgemm<false, false, false, false><<<g, blk, SMEM_B>>>(qp, kp, nullptr, nullptr, sp,
            H_, H_, H_, S_,
            (size_t)S_ * H_, (size_t)S_ * H_, (size_t)S_ * S_, 0.03125f);
    }

    // --- softmax (output tf32-rounded) ---
    softmax_k<<<NTOK, blk>>>(sp, mask);

    // --- V^T per batch (rounded) ---
    transpose_k<<<dim3(H_ / 32, S_ / 32, B_), blk>>>(vp, vt, S_, H_);

    // --- attn = a @ v ---
    {
        dim3 g(H_ / 256, S_ / 128, B_);
        tgemm<false, false, false, false><<<g, blk, SMEM_B>>>(sp, vt, nullptr, nullptr, ap,
            S_, S_, S_, H_,
            (size_t)S_ * S_, (size_t)S_ * H_, (size_t)S_ * H_, 1.0f);
    }

    // --- FFN1: h = relu(attn @ w1 + b1), stored tf32-rounded ---
    {
        dim3 g(F_ / 256, NTOK / 128, 1);
        tgemm<true, true, false, true><<<g, blk, SMEM_B>>>(ap, w1t, b1, nullptr, hp,
            H_, H_, H_, F_, 0, 0, 0, 1.0f);
    }

    // --- FFN2 + residual ---
    {
        dim3 g(H_ / 256, NTOK / 128, 1);
        tgemm<true, false, true, false><<<g, blk, SMEM_B>>>(hp, w2t, b2, ap, yp,
            F_, F_, F_, H_, 0, 0, 0, 1.0f);
    }

    // --- LayerNorm ---
    ln_k<<<NTOK, blk>>>(yp, gamma, beta, out);
}

// round 5
// speedup vs baseline: 3.3232x; 1.0866x over previous
#include <cuda_runtime.h>
#include <cstdint>
#include <math.h>

#define B_   4
#define S_   2048
#define H_   1024
#define F_   4096
#define NTOK (B_ * S_)   // 8192

// ---------------------------------------------------------------------------
// Scratch (static device globals)
// ---------------------------------------------------------------------------
__device__ float g_xr[(size_t)NTOK * H_];
__device__ float g_q[(size_t)NTOK * H_];
__device__ float g_k[(size_t)NTOK * H_];
__device__ float g_v[(size_t)NTOK * H_];
__device__ float g_s[(size_t)B_ * S_ * S_];
__device__ float g_attn[(size_t)NTOK * H_];
__device__ float g_h[(size_t)NTOK * F_];
__device__ float g_y[(size_t)NTOK * H_];
__device__ float g_wqt[(size_t)H_ * H_];
__device__ float g_wkt[(size_t)H_ * H_];
__device__ float g_wvt[(size_t)H_ * H_];
__device__ float g_w1t[(size_t)H_ * F_];
__device__ float g_w2t[(size_t)F_ * H_];
__device__ float g_vt[(size_t)NTOK * H_];

// ---------------------------------------------------------------------------
// Helpers
// ---------------------------------------------------------------------------
__device__ __forceinline__ uint32_t f2tf(float f) {
    uint32_t r;
    asm("cvt.rna.tf32.f32 %0, %1;" : "=r"(r) : "f"(f));
    return r;
}
__device__ __forceinline__ float f2tff(float f) {
    return __uint_as_float(f2tf(f));
}
__device__ __forceinline__ uint32_t smem_u32(const void* p) {
    uint32_t a;
    asm("{ .reg .u64 t; cvta.to.shared.u64 t, %1; cvt.u32.u64 %0, t; }" : "=r"(a) : "l"(p));
    return a;
}
__device__ __forceinline__ void cp16(uint32_t s, const void* g) {
    asm volatile("cp.async.cg.shared.global [%0], [%1], 16;" :: "r"(s), "l"(g) : "memory");
}
#define CP_COMMIT() asm volatile("cp.async.commit_group;" ::: "memory")
#define CP_WAIT2()  asm volatile("cp.async.wait_group 2;" ::: "memory")

__device__ __forceinline__ void mma8(float c[4], const uint32_t a[4], const uint32_t b[2]) {
    asm volatile("mma.sync.aligned.m16n8k8.row.col.f32.tf32.tf32.f32 "
                 "{%0,%1,%2,%3}, {%4,%5,%6,%7}, {%8,%9}, {%0,%1,%2,%3};"
                 : "+f"(c[0]), "+f"(c[1]), "+f"(c[2]), "+f"(c[3])
                 : "r"(a[0]), "r"(a[1]), "r"(a[2]), "r"(a[3]), "r"(b[0]), "r"(b[1]));
}
__device__ __forceinline__ void ldsm4(uint32_t r[4], uint32_t addr) {
    asm volatile("ldmatrix.sync.aligned.m8n8.x4.shared.b16 {%0,%1,%2,%3}, [%4];"
                 : "=r"(r[0]), "=r"(r[1]), "=r"(r[2]), "=r"(r[3]) : "r"(addr));
}

// ---------------------------------------------------------------------------
// TF32 tensor-core GEMM, cp.async 4-stage pipeline, ldmatrix fragment loads:
//   C = alpha * A[M,K] * Bw[N,K]^T (+bias) (+res) (relu) (round-to-tf32 store)
// CTA tile 128x256, BK=16, 8 warps (2x4), warp tile 64x64.
// All GEMM inputs must already be tf32-rounded in gmem (cp.async copies raw).
// M mult of 128, N mult of 256, K mult of 16. Batched over blockIdx.z.
// Smem per stage: (128+256) rows x 20 u32 = 30720 B; 4 stages = 122880 B.
// ---------------------------------------------------------------------------
#define LDSS 20
#define STAGE_U32 (128 * LDSS + 256 * LDSS)     // 7680
#define STAGE_B   (STAGE_U32 * 4)               // 30720
#define NSTAGE 4
#define SMEM_B    (NSTAGE * STAGE_B)            // 122880

template <bool BIAS, bool RELU, bool RES, bool ROUND>
__global__ __launch_bounds__(256, 1) void tgemm(
    const float* __restrict__ A, const float* __restrict__ Bw,
    const float* __restrict__ bias, const float* __restrict__ res,
    float* __restrict__ C,
    int K, int lda, int ldb, int ldc,
    size_t sA, size_t sB, size_t sC, float alpha)
{
    extern __shared__ uint32_t smem[];
    const uint32_t sbase = smem_u32(smem);

    const int tid  = threadIdx.x;
    const int wid  = tid >> 5, lane = tid & 31;
    const int g    = lane >> 2, t4 = lane & 3;
    const int warpM = wid >> 2, warpN = wid & 3;

    const int z = blockIdx.z;
    A  += (size_t)z * sA;
    Bw += (size_t)z * sB;
    C  += (size_t)z * sC;
    const float* Rp = RES ? (res + (size_t)z * sC) : nullptr;

    const int n0 = blockIdx.x << 8, m0 = blockIdx.y << 7;
    const float* Ap = A  + (size_t)m0 * lda;
    const float* Bp = Bw + (size_t)n0 * ldb;

    const int KT = K >> 4;

    auto issue = [&](int kt) {
        const uint32_t s = sbase + (uint32_t)(kt % NSTAGE) * STAGE_B;
        const int kb = kt << 4;
#pragma unroll
        for (int j = 0; j < 2; j++) {
            const int c = tid + (j << 8);
            const int row = c >> 2, c4 = (c & 3) << 2;
            cp16(s + (uint32_t)((row * LDSS + c4) << 2),
                 Ap + (size_t)row * lda + kb + c4);
        }
        const uint32_t sB2 = s + (uint32_t)(128 * LDSS * 4);
#pragma unroll
        for (int j = 0; j < 4; j++) {
            const int c = tid + (j << 8);
            const int row = c >> 2, c4 = (c & 3) << 2;
            cp16(sB2 + (uint32_t)((row * LDSS + c4) << 2),
                 Bp + (size_t)row * ldb + kb + c4);
        }
    };

    // ldmatrix per-lane source offsets (u32-element units within a tile)
    // A (per mt): tiles = {rows 0-7,k0-3}{rows 8-15,k0-3}{rows 0-7,k4-7}{rows 8-15,k4-7}
    const int aRowOff = (((lane >> 3) & 1) << 3) + (lane & 7);
    const int aKwOff  = (lane >> 4) << 2;
    // B (per nt-pair): tiles = {n 0-7,k0-3}{n 0-7,k4-7}{n 8-15,k0-3}{n 8-15,k4-7}
    const int bRowOff = ((lane >> 4) << 3) + (lane & 7);
    const int bKwOff  = ((lane >> 3) & 1) << 2;

    const uint32_t aLane = sbase
        + (uint32_t)(((warpM * 64 + aRowOff) * LDSS + aKwOff) << 2);
    const uint32_t bLane = sbase + (uint32_t)(128 * LDSS * 4)
        + (uint32_t)(((warpN * 64 + bRowOff) * LDSS + bKwOff) << 2);

    float acc[4][8][4];
#pragma unroll
    for (int mt = 0; mt < 4; mt++)
#pragma unroll
        for (int nt = 0; nt < 8; nt++)
#pragma unroll
            for (int i = 0; i < 4; i++) acc[mt][nt][i] = 0.0f;

    // prologue: stages 0..2
    issue(0); CP_COMMIT();
    if (KT > 1) issue(1);
    CP_COMMIT();
    if (KT > 2) issue(2);
    CP_COMMIT();

    for (int kt = 0; kt < KT; kt++) {
        CP_WAIT2();
        __syncthreads();

        if (kt + 3 < KT) issue(kt + 3);
        CP_COMMIT();

        const uint32_t stOff = (uint32_t)((kt % NSTAGE) * STAGE_B);

#pragma unroll
        for (int ks = 0; ks < 2; ks++) {
            uint32_t afr[4][4], bfr[8][2];
#pragma unroll
            for (int mt = 0; mt < 4; mt++)
                ldsm4(afr[mt], aLane + stOff + (uint32_t)(((mt * 16 * LDSS) + ks * 8) << 2));
#pragma unroll
            for (int p = 0; p < 4; p++) {
                uint32_t r[4];
                ldsm4(r, bLane + stOff + (uint32_t)(((p * 16 * LDSS) + ks * 8) << 2));
                bfr[2 * p][0] = r[0]; bfr[2 * p][1] = r[1];
                bfr[2 * p + 1][0] = r[2]; bfr[2 * p + 1][1] = r[3];
            }
#pragma unroll
            for (int mt = 0; mt < 4; mt++)
#pragma unroll
                for (int nt = 0; nt < 8; nt++)
                    mma8(acc[mt][nt], afr[mt], bfr[nt]);
        }
    }

    // --- fused epilogue, direct float2 stores ---
    const int rbase = m0 + warpM * 64;
    const int cbase = n0 + warpN * 64;
#pragma unroll
    for (int mt = 0; mt < 4; mt++) {
#pragma unroll
        for (int nt = 0; nt < 8; nt++) {
            const int col = cbase + nt * 8 + (t4 << 1);
            float bx = 0.f, by = 0.f;
            if (BIAS) {
                float2 bb = *(const float2*)(bias + col);
                bx = bb.x; by = bb.y;
            }
#pragma unroll
            for (int hh = 0; hh < 2; hh++) {
                const int row = rbase + mt * 16 + g + hh * 8;
                float v0 = acc[mt][nt][hh * 2 + 0] * alpha;
                float v1 = acc[mt][nt][hh * 2 + 1] * alpha;
                if (BIAS) { v0 += bx; v1 += by; }
                if (RES) {
                    float2 rr = *(const float2*)(Rp + (size_t)row * ldc + col);
                    v0 += rr.x; v1 += rr.y;
                }
                if (RELU) { v0 = fmaxf(v0, 0.f); v1 = fmaxf(v1, 0.f); }
                if (ROUND) { v0 = f2tff(v0); v1 = f2tff(v1); }
                float2 o; o.x = v0; o.y = v1;
                *(float2*)(C + (size_t)row * ldc + col) = o;
            }
        }
    }
}

// ---------------------------------------------------------------------------
// Elementwise tf32 round
// ---------------------------------------------------------------------------
__global__ __launch_bounds__(256) void round_k(const float* __restrict__ in,
                                               float* __restrict__ out)
{
    const size_t i = ((size_t)blockIdx.x * 256 + threadIdx.x) * 4;
    float4 v = *(const float4*)(in + i);
    v.x = f2tff(v.x); v.y = f2tff(v.y); v.z = f2tff(v.z); v.w = f2tff(v.w);
    *(float4*)(out + i) = v;
}

// ---------------------------------------------------------------------------
// Transpose + tf32 round: src [R,C] -> dst [C,R], batched over z.
// ---------------------------------------------------------------------------
__global__ __launch_bounds__(256) void transpose_k(const float* __restrict__ src,
                                                   float* __restrict__ dst, int R, int C)
{
    __shared__ float t[32][33];
    const size_t zoff = (size_t)blockIdx.z * R * C;
    src += zoff; dst += zoff;
    const int bx = blockIdx.x << 5, by = blockIdx.y << 5;
    const int tx = threadIdx.x & 31, ty = (threadIdx.x >> 5) << 2;
#pragma unroll
    for (int j = 0; j < 4; j++)
        t[ty + j][tx] = src[(size_t)(by + ty + j) * C + bx + tx];
    __syncthreads();
#pragma unroll
    for (int j = 0; j < 4; j++)
        dst[(size_t)(bx + ty + j) * R + by + tx] = f2tff(t[tx][ty + j]);
}

// ---------------------------------------------------------------------------
// Row softmax (S_ wide) with mask; output rounded to tf32
// ---------------------------------------------------------------------------
__global__ __launch_bounds__(256) void softmax_k(float* __restrict__ s,
                                                 const float* __restrict__ mask)
{
    const int row = blockIdx.x;
    const int q   = row & (S_ - 1);
    float* p = s + (size_t)row * S_;
    const float* mrow = mask + (size_t)q * S_;
    const int tid = threadIdx.x;
    __shared__ float red[256];

    float vals[8];
    float vmax = -3.0e38f;
#pragma unroll
    for (int i = 0; i < 8; i++) {
        const int idx = tid + i * 256;
        const float v = p[idx] + mrow[idx];
        vals[i] = v;
        vmax = fmaxf(vmax, v);
    }
    red[tid] = vmax; __syncthreads();
    for (int o = 128; o > 0; o >>= 1) {
        if (tid < o) red[tid] = fmaxf(red[tid], red[tid + o]);
        __syncthreads();
    }
    vmax = red[0]; __syncthreads();
    float sum = 0.0f;
#pragma unroll
    for (int i = 0; i < 8; i++) { const float e = __expf(vals[i] - vmax); vals[i] = e; sum += e; }
    red[tid] = sum; __syncthreads();
    for (int o = 128; o > 0; o >>= 1) {
        if (tid < o) red[tid] += red[tid + o];
        __syncthreads();
    }
    const float inv = 1.0f / red[0];
#pragma unroll
    for (int i = 0; i < 8; i++) p[tid + i * 256] = f2tff(vals[i] * inv);
}

// ---------------------------------------------------------------------------
// LayerNorm (H_=1024)
// ---------------------------------------------------------------------------
__global__ __launch_bounds__(256) void ln_k(const float* __restrict__ y,
                                            const float* __restrict__ gamma,
                                            const float* __restrict__ beta,
                                            float* __restrict__ out)
{
    const int row = blockIdx.x;
    const float4* p4 = (const float4*)(y + (size_t)row * H_);
    const int tid = threadIdx.x;
    __shared__ float rs[256], rq[256];

    const float4 v = p4[tid];
    rs[tid] = v.x + v.y + v.z + v.w;
    rq[tid] = v.x * v.x + v.y * v.y + v.z * v.z + v.w * v.w;
    __syncthreads();
    for (int o = 128; o > 0; o >>= 1) {
        if (tid < o) { rs[tid] += rs[tid + o]; rq[tid] += rq[tid + o]; }
        __syncthreads();
    }
    const float mu  = rs[0] * (1.0f / H_);
    const float var = rq[0] * (1.0f / H_) - mu * mu;
    const float inv = rsqrtf(var + 1e-5f);
    const float4 g = ((const float4*)gamma)[tid];
    const float4 b = ((const float4*)beta)[tid];
    float4 o;
    o.x = (v.x - mu) * inv * g.x + b.x;
    o.y = (v.y - mu) * inv * g.y + b.y;
    o.z = (v.z - mu) * inv * g.z + b.z;
    o.w = (v.w - mu) * inv * g.w + b.w;
    ((float4*)(out + (size_t)row * H_))[tid] = o;
}

// ---------------------------------------------------------------------------
// Launch
// ---------------------------------------------------------------------------
extern "C" void kernel_launch(void* const* d_in, const int* in_sizes, int n_in,
                              void* d_out, int out_size)
{
    const float* x     = (const float*)d_in[0];
    const float* mask  = (const float*)d_in[1];
    const float* qW    = (const float*)d_in[2];
    const float* qb    = (const float*)d_in[3];
    const float* kW    = (const float*)d_in[4];
    const float* kb    = (const float*)d_in[5];
    const float* vW    = (const float*)d_in[6];
    const float* vb    = (const float*)d_in[7];
    const float* w1    = (const float*)d_in[8];
    const float* b1    = (const float*)d_in[9];
    const float* w2    = (const float*)d_in[10];
    const float* b2    = (const float*)d_in[11];
    const float* gamma = (const float*)d_in[12];
    const float* beta  = (const float*)d_in[13];
    float* out = (float*)d_out;

    float *xr, *qp, *kp, *vp, *sp, *ap, *hp, *yp;
    float *wqt, *wkt, *wvt, *w1t, *w2t, *vt;
    cudaGetSymbolAddress((void**)&xr, g_xr);
    cudaGetSymbolAddress((void**)&qp, g_q);
    cudaGetSymbolAddress((void**)&kp, g_k);
    cudaGetSymbolAddress((void**)&vp, g_v);
    cudaGetSymbolAddress((void**)&sp, g_s);
    cudaGetSymbolAddress((void**)&ap, g_attn);
    cudaGetSymbolAddress((void**)&hp, g_h);
    cudaGetSymbolAddress((void**)&yp, g_y);
    cudaGetSymbolAddress((void**)&wqt, g_wqt);
    cudaGetSymbolAddress((void**)&wkt, g_wkt);
    cudaGetSymbolAddress((void**)&wvt, g_wvt);
    cudaGetSymbolAddress((void**)&w1t, g_w1t);
    cudaGetSymbolAddress((void**)&w2t, g_w2t);
    cudaGetSymbolAddress((void**)&vt, g_vt);

    cudaFuncSetAttribute((const void*)tgemm<true,  false, false, true >,
                         cudaFuncAttributeMaxDynamicSharedMemorySize, SMEM_B);
    cudaFuncSetAttribute((const void*)tgemm<true,  false, false, false>,
                         cudaFuncAttributeMaxDynamicSharedMemorySize, SMEM_B);
    cudaFuncSetAttribute((const void*)tgemm<false, false, false, false>,
                         cudaFuncAttributeMaxDynamicSharedMemorySize, SMEM_B);
    cudaFuncSetAttribute((const void*)tgemm<true,  true,  false, true >,
                         cudaFuncAttributeMaxDynamicSharedMemorySize, SMEM_B);
    cudaFuncSetAttribute((const void*)tgemm<true,  false, true,  false>,
                         cudaFuncAttributeMaxDynamicSharedMemorySize, SMEM_B);

    const dim3 blk(256);

    // --- pre-round x; transpose+round weights to [N,K] ---
    round_k<<<(NTOK * H_) / 1024, blk>>>(x, xr);
    transpose_k<<<dim3(H_ / 32, H_ / 32, 1), blk>>>(qW, wqt, H_, H_);
    transpose_k<<<dim3(H_ / 32, H_ / 32, 1), blk>>>(kW, wkt, H_, H_);
    transpose_k<<<dim3(H_ / 32, H_ / 32, 1), blk>>>(vW, wvt, H_, H_);
    transpose_k<<<dim3(F_ / 32, H_ / 32, 1), blk>>>(w1, w1t, H_, F_);
    transpose_k<<<dim3(H_ / 32, F_ / 32, 1), blk>>>(w2, w2t, F_, H_);

    // --- QKV projections (q,k stored tf32-rounded; v raw, rounded in vt) ---
    {
        dim3 g(H_ / 256, NTOK / 128, 1);
        tgemm<true, false, false, true ><<<g, blk, SMEM_B>>>(xr, wqt, qb, nullptr, qp,
            H_, H_, H_, H_, 0, 0, 0, 1.0f);
        tgemm<true, false, false, true ><<<g, blk, SMEM_B>>>(xr, wkt, kb, nullptr, kp,
            H_, H_, H_, H_, 0, 0, 0, 1.0f);
        tgemm<true, false, false, false><<<g, blk, SMEM_B>>>(xr, wvt, vb, nullptr, vp,
            H_, H_, H_, H_, 0, 0, 0, 1.0f);
    }

    // --- scores: per batch S = q @ k^T / sqrt(H) ---
    {
        dim3 g(S_ / 256, S_ / 128, B_);
        tgemm<false, false, false, false><<<g, blk, SMEM_B>>>(qp, kp, nullptr, nullptr, sp,
            H_, H_, H_, S_,
            (size_t)S_ * H_, (size_t)S_ * H_, (size_t)S_ * S_, 0.03125f);
    }

    // --- softmax (output tf32-rounded) ---
    softmax_k<<<NTOK, blk>>>(sp, mask);

    // --- V^T per batch (rounded) ---
    transpose_k<<<dim3(H_ / 32, S_ / 32, B_), blk>>>(vp, vt, S_, H_);

    // --- attn = a @ v ---
    {
        dim3 g(H_ / 256, S_ / 128, B_);
        tgemm<false, false, false, false><<<g, blk, SMEM_B>>>(sp, vt, nullptr, nullptr, ap,
            S_, S_, S_, H_,
            (size_t)S_ * S_, (size_t)S_ * H_, (size_t)S_ * H_, 1.0f);
    }

    // --- FFN1: h = relu(attn @ w1 + b1), stored tf32-rounded ---
    {
        dim3 g(F_ / 256, NTOK / 128, 1);
        tgemm<true, true, false, true><<<g, blk, SMEM_B>>>(ap, w1t, b1, nullptr, hp,
            H_, H_, H_, F_, 0, 0, 0, 1.0f);
    }

    // --- FFN2 + residual ---
    {
        dim3 g(H_ / 256, NTOK / 128, 1);
        tgemm<true, false, true, false><<<g, blk, SMEM_B>>>(hp, w2t, b2, ap, yp,
            F_, F_, F_, H_, 0, 0, 0, 1.0f);
    }

    // --- LayerNorm ---
    ln_k<<<NTOK, blk>>>(yp, gamma, beta, out);
}

// round 6
// speedup vs baseline: 3.3470x; 1.0071x over previous
#include <cuda_runtime.h>
#include <cstdint>
#include <math.h>

#define B_   4
#define S_   2048
#define H_   1024
#define F_   4096
#define NTOK (B_ * S_)   // 8192

// ---------------------------------------------------------------------------
// Scratch (static device globals)
// ---------------------------------------------------------------------------
__device__ float g_xr[(size_t)NTOK * H_];
__device__ float g_qk[(size_t)NTOK * 2 * H_];     // [8192, 2048]: q | k
__device__ float g_s[(size_t)B_ * S_ * S_];
__device__ float g_attn[(size_t)NTOK * H_];
__device__ float g_h[(size_t)NTOK * F_];
__device__ float g_y[(size_t)NTOK * H_];
__device__ float g_wqkt[(size_t)2 * H_ * H_];     // [2048, 1024]: wq^T | wk^T
__device__ float g_wvt[(size_t)H_ * H_];
__device__ float g_w1t[(size_t)H_ * F_];
__device__ float g_w2t[(size_t)F_ * H_];
__device__ float g_vt[(size_t)H_ * NTOK];         // [1024, 8192] V^T, all batches
__device__ float g_qkb[2 * H_];

// ---------------------------------------------------------------------------
// Helpers
// ---------------------------------------------------------------------------
__device__ __forceinline__ uint32_t f2tf(float f) {
    uint32_t r;
    asm("cvt.rna.tf32.f32 %0, %1;" : "=r"(r) : "f"(f));
    return r;
}
__device__ __forceinline__ float f2tff(float f) {
    return __uint_as_float(f2tf(f));
}
__device__ __forceinline__ uint32_t smem_u32(const void* p) {
    uint32_t a;
    asm("{ .reg .u64 t; cvta.to.shared.u64 t, %1; cvt.u32.u64 %0, t; }" : "=r"(a) : "l"(p));
    return a;
}
__device__ __forceinline__ void cp16(uint32_t s, const void* g) {
    asm volatile("cp.async.cg.shared.global [%0], [%1], 16;" :: "r"(s), "l"(g) : "memory");
}
#define CP_COMMIT() asm volatile("cp.async.commit_group;" ::: "memory")
#define CP_WAIT2()  asm volatile("cp.async.wait_group 2;" ::: "memory")

__device__ __forceinline__ void mma8(float c[4], const uint32_t a[4], const uint32_t b[2]) {
    asm volatile("mma.sync.aligned.m16n8k8.row.col.f32.tf32.tf32.f32 "
                 "{%0,%1,%2,%3}, {%4,%5,%6,%7}, {%8,%9}, {%0,%1,%2,%3};"
                 : "+f"(c[0]), "+f"(c[1]), "+f"(c[2]), "+f"(c[3])
                 : "r"(a[0]), "r"(a[1]), "r"(a[2]), "r"(a[3]), "r"(b[0]), "r"(b[1]));
}
__device__ __forceinline__ void ldsm4(uint32_t r[4], uint32_t addr) {
    asm volatile("ldmatrix.sync.aligned.m8n8.x4.shared.b16 {%0,%1,%2,%3}, [%4];"
                 : "=r"(r[0]), "=r"(r[1]), "=r"(r[2]), "=r"(r[3]) : "r"(addr));
}

// ---------------------------------------------------------------------------
// TF32 tensor-core GEMM, cp.async 4-stage pipeline, ldmatrix fragment loads:
//   C = alpha * A[M,K] * Bw[N,K]^T (+bias[N]) (+biasM[M]) (+res) (relu) (round)
// CTA tile 128x256, BK=16, 8 warps (2x4), warp tile 64x64.
// M mult of 128, N mult of 256, K mult of 16. Batched over blockIdx.z.
// ---------------------------------------------------------------------------
#define LDSS 20
#define STAGE_U32 (128 * LDSS + 256 * LDSS)     // 7680
#define STAGE_B   (STAGE_U32 * 4)               // 30720
#define NSTAGE 4
#define SMEM_B    (NSTAGE * STAGE_B)            // 122880

template <bool BIAS, bool RELU, bool RES, bool ROUND, bool BIASM>
__global__ __launch_bounds__(256, 1) void tgemm(
    const float* __restrict__ A, const float* __restrict__ Bw,
    const float* __restrict__ bias, const float* __restrict__ res,
    float* __restrict__ C,
    int K, int lda, int ldb, int ldc,
    size_t sA, size_t sB, size_t sC, float alpha)
{
    extern __shared__ uint32_t smem[];
    const uint32_t sbase = smem_u32(smem);

    const int tid  = threadIdx.x;
    const int wid  = tid >> 5, lane = tid & 31;
    const int g    = lane >> 2, t4 = lane & 3;
    const int warpM = wid >> 2, warpN = wid & 3;

    const int z = blockIdx.z;
    A  += (size_t)z * sA;
    Bw += (size_t)z * sB;
    C  += (size_t)z * sC;
    const float* Rp = RES ? (res + (size_t)z * sC) : nullptr;

    const int n0 = blockIdx.x << 8, m0 = blockIdx.y << 7;
    const float* Ap = A  + (size_t)m0 * lda;
    const float* Bp = Bw + (size_t)n0 * ldb;

    const int KT = K >> 4;

    auto issue = [&](int kt) {
        const uint32_t s = sbase + (uint32_t)(kt % NSTAGE) * STAGE_B;
        const int kb = kt << 4;
#pragma unroll
        for (int j = 0; j < 2; j++) {
            const int c = tid + (j << 8);
            const int row = c >> 2, c4 = (c & 3) << 2;
            cp16(s + (uint32_t)((row * LDSS + c4) << 2),
                 Ap + (size_t)row * lda + kb + c4);
        }
        const uint32_t sB2 = s + (uint32_t)(128 * LDSS * 4);
#pragma unroll
        for (int j = 0; j < 4; j++) {
            const int c = tid + (j << 8);
            const int row = c >> 2, c4 = (c & 3) << 2;
            cp16(sB2 + (uint32_t)((row * LDSS + c4) << 2),
                 Bp + (size_t)row * ldb + kb + c4);
        }
    };

    // ldmatrix per-lane source offsets
    const int aRowOff = (((lane >> 3) & 1) << 3) + (lane & 7);
    const int aKwOff  = (lane >> 4) << 2;
    const int bRowOff = ((lane >> 4) << 3) + (lane & 7);
    const int bKwOff  = ((lane >> 3) & 1) << 2;

    const uint32_t aLane = sbase
        + (uint32_t)(((warpM * 64 + aRowOff) * LDSS + aKwOff) << 2);
    const uint32_t bLane = sbase + (uint32_t)(128 * LDSS * 4)
        + (uint32_t)(((warpN * 64 + bRowOff) * LDSS + bKwOff) << 2);

    float acc[4][8][4];
#pragma unroll
    for (int mt = 0; mt < 4; mt++)
#pragma unroll
        for (int nt = 0; nt < 8; nt++)
#pragma unroll
            for (int i = 0; i < 4; i++) acc[mt][nt][i] = 0.0f;

    issue(0); CP_COMMIT();
    if (KT > 1) issue(1);
    CP_COMMIT();
    if (KT > 2) issue(2);
    CP_COMMIT();

    for (int kt = 0; kt < KT; kt++) {
        CP_WAIT2();
        __syncthreads();

        if (kt + 3 < KT) issue(kt + 3);
        CP_COMMIT();

        const uint32_t stOff = (uint32_t)((kt % NSTAGE) * STAGE_B);

#pragma unroll
        for (int ks = 0; ks < 2; ks++) {
            uint32_t afr[4][4], bfr[8][2];
#pragma unroll
            for (int mt = 0; mt < 4; mt++)
                ldsm4(afr[mt], aLane + stOff + (uint32_t)(((mt * 16 * LDSS) + ks * 8) << 2));
#pragma unroll
            for (int p = 0; p < 4; p++) {
                uint32_t r[4];
                ldsm4(r, bLane + stOff + (uint32_t)(((p * 16 * LDSS) + ks * 8) << 2));
                bfr[2 * p][0] = r[0]; bfr[2 * p][1] = r[1];
                bfr[2 * p + 1][0] = r[2]; bfr[2 * p + 1][1] = r[3];
            }
#pragma unroll
            for (int mt = 0; mt < 4; mt++)
#pragma unroll
                for (int nt = 0; nt < 8; nt++)
                    mma8(acc[mt][nt], afr[mt], bfr[nt]);
        }
    }

    // --- fused epilogue ---
    const int rbase = m0 + warpM * 64;
    const int cbase = n0 + warpN * 64;
#pragma unroll
    for (int mt = 0; mt < 4; mt++) {
#pragma unroll
        for (int nt = 0; nt < 8; nt++) {
            const int col = cbase + nt * 8 + (t4 << 1);
            float bx = 0.f, by = 0.f;
            if (BIAS) {
                float2 bb = *(const float2*)(bias + col);
                bx = bb.x; by = bb.y;
            }
#pragma unroll
            for (int hh = 0; hh < 2; hh++) {
                const int row = rbase + mt * 16 + g + hh * 8;
                float v0 = acc[mt][nt][hh * 2 + 0] * alpha;
                float v1 = acc[mt][nt][hh * 2 + 1] * alpha;
                if (BIAS) { v0 += bx; v1 += by; }
                if (BIASM) { const float bm = bias[row]; v0 += bm; v1 += bm; }
                if (RES) {
                    float2 rr = *(const float2*)(Rp + (size_t)row * ldc + col);
                    v0 += rr.x; v1 += rr.y;
                }
                if (RELU) { v0 = fmaxf(v0, 0.f); v1 = fmaxf(v1, 0.f); }
                if (ROUND) { v0 = f2tff(v0); v1 = f2tff(v1); }
                float2 o; o.x = v0; o.y = v1;
                *(float2*)(C + (size_t)row * ldc + col) = o;
            }
        }
    }
}

// ---------------------------------------------------------------------------
// Elementwise tf32 round
// ---------------------------------------------------------------------------
__global__ __launch_bounds__(256) void round_k(const float* __restrict__ in,
                                               float* __restrict__ out)
{
    const size_t i = ((size_t)blockIdx.x * 256 + threadIdx.x) * 4;
    float4 v = *(const float4*)(in + i);
    v.x = f2tff(v.x); v.y = f2tff(v.y); v.z = f2tff(v.z); v.w = f2tff(v.w);
    *(float4*)(out + i) = v;
}

// ---------------------------------------------------------------------------
// Concat two H_-vectors (bias) into one 2H_ vector
// ---------------------------------------------------------------------------
__global__ __launch_bounds__(256) void catbias_k(const float* __restrict__ a,
                                                 const float* __restrict__ b,
                                                 float* __restrict__ out)
{
    const int i = blockIdx.x * 256 + threadIdx.x;
    out[i] = (i < H_) ? a[i] : b[i - H_];
}

// ---------------------------------------------------------------------------
// Transpose + tf32 round: src [R,C] -> dst [C,R]
// ---------------------------------------------------------------------------
__global__ __launch_bounds__(256) void transpose_k(const float* __restrict__ src,
                                                   float* __restrict__ dst, int R, int C)
{
    __shared__ float t[32][33];
    const int bx = blockIdx.x << 5, by = blockIdx.y << 5;
    const int tx = threadIdx.x & 31, ty = (threadIdx.x >> 5) << 2;
#pragma unroll
    for (int j = 0; j < 4; j++)
        t[ty + j][tx] = src[(size_t)(by + ty + j) * C + bx + tx];
    __syncthreads();
#pragma unroll
    for (int j = 0; j < 4; j++)
        dst[(size_t)(bx + ty + j) * R + by + tx] = f2tff(t[tx][ty + j]);
}

// ---------------------------------------------------------------------------
// Row softmax (S_ wide) with mask; output rounded to tf32
// ---------------------------------------------------------------------------
__global__ __launch_bounds__(256) void softmax_k(float* __restrict__ s,
                                                 const float* __restrict__ mask)
{
    const int row = blockIdx.x;
    const int q   = row & (S_ - 1);
    float* p = s + (size_t)row * S_;
    const float* mrow = mask + (size_t)q * S_;
    const int tid = threadIdx.x;
    __shared__ float red[256];

    float vals[8];
    float vmax = -3.0e38f;
#pragma unroll
    for (int i = 0; i < 8; i++) {
        const int idx = tid + i * 256;
        const float v = p[idx] + mrow[idx];
        vals[i] = v;
        vmax = fmaxf(vmax, v);
    }
    red[tid] = vmax; __syncthreads();
    for (int o = 128; o > 0; o >>= 1) {
        if (tid < o) red[tid] = fmaxf(red[tid], red[tid + o]);
        __syncthreads();
    }
    vmax = red[0]; __syncthreads();
    float sum = 0.0f;
#pragma unroll
    for (int i = 0; i < 8; i++) { const float e = __expf(vals[i] - vmax); vals[i] = e; sum += e; }
    red[tid] = sum; __syncthreads();
    for (int o = 128; o > 0; o >>= 1) {
        if (tid < o) red[tid] += red[tid + o];
        __syncthreads();
    }
    const float inv = 1.0f / red[0];
#pragma unroll
    for (int i = 0; i < 8; i++) p[tid + i * 256] = f2tff(vals[i] * inv);
}

// ---------------------------------------------------------------------------
// LayerNorm (H_=1024)
// ---------------------------------------------------------------------------
__global__ __launch_bounds__(256) void ln_k(const float* __restrict__ y,
                                            const float* __restrict__ gamma,
                                            const float* __restrict__ beta,
                                            float* __restrict__ out)
{
    const int row = blockIdx.x;
    const float4* p4 = (const float4*)(y + (size_t)row * H_);
    const int tid = threadIdx.x;
    __shared__ float rs[256], rq[256];

    const float4 v = p4[tid];
    rs[tid] = v.x + v.y + v.z + v.w;
    rq[tid] = v.x * v.x + v.y * v.y + v.z * v.z + v.w * v.w;
    __syncthreads();
    for (int o = 128; o > 0; o >>= 1) {
        if (tid < o) { rs[tid] += rs[tid + o]; rq[tid] += rq[tid + o]; }
        __syncthreads();
    }
    const float mu  = rs[0] * (1.0f / H_);
    const float var = rq[0] * (1.0f / H_) - mu * mu;
    const float inv = rsqrtf(var + 1e-5f);
    const float4 g = ((const float4*)gamma)[tid];
    const float4 b = ((const float4*)beta)[tid];
    float4 o;
    o.x = (v.x - mu) * inv * g.x + b.x;
    o.y = (v.y - mu) * inv * g.y + b.y;
    o.z = (v.z - mu) * inv * g.z + b.z;
    o.w = (v.w - mu) * inv * g.w + b.w;
    ((float4*)(out + (size_t)row * H_))[tid] = o;
}

// ---------------------------------------------------------------------------
// Launch
// ---------------------------------------------------------------------------
extern "C" void kernel_launch(void* const* d_in, const int* in_sizes, int n_in,
                              void* d_out, int out_size)
{
    const float* x     = (const float*)d_in[0];
    const float* mask  = (const float*)d_in[1];
    const float* qW    = (const float*)d_in[2];
    const float* qb    = (const float*)d_in[3];
    const float* kW    = (const float*)d_in[4];
    const float* kb    = (const float*)d_in[5];
    const float* vW    = (const float*)d_in[6];
    const float* vb    = (const float*)d_in[7];
    const float* w1    = (const float*)d_in[8];
    const float* b1    = (const float*)d_in[9];
    const float* w2    = (const float*)d_in[10];
    const float* b2    = (const float*)d_in[11];
    const float* gamma = (const float*)d_in[12];
    const float* beta  = (const float*)d_in[13];
    float* out = (float*)d_out;

    float *xr, *qk, *sp, *ap, *hp, *yp;
    float *wqkt, *wvt, *w1t, *w2t, *vt, *qkb;
    cudaGetSymbolAddress((void**)&xr, g_xr);
    cudaGetSymbolAddress((void**)&qk, g_qk);
    cudaGetSymbolAddress((void**)&sp, g_s);
    cudaGetSymbolAddress((void**)&ap, g_attn);
    cudaGetSymbolAddress((void**)&hp, g_h);
    cudaGetSymbolAddress((void**)&yp, g_y);
    cudaGetSymbolAddress((void**)&wqkt, g_wqkt);
    cudaGetSymbolAddress((void**)&wvt, g_wvt);
    cudaGetSymbolAddress((void**)&w1t, g_w1t);
    cudaGetSymbolAddress((void**)&w2t, g_w2t);
    cudaGetSymbolAddress((void**)&vt, g_vt);
    cudaGetSymbolAddress((void**)&qkb, g_qkb);

    cudaFuncSetAttribute((const void*)tgemm<true,  false, false, true,  false>,
                         cudaFuncAttributeMaxDynamicSharedMemorySize, SMEM_B);
    cudaFuncSetAttribute((const void*)tgemm<false, false, false, true,  true >,
                         cudaFuncAttributeMaxDynamicSharedMemorySize, SMEM_B);
    cudaFuncSetAttribute((const void*)tgemm<false, false, false, false, false>,
                         cudaFuncAttributeMaxDynamicSharedMemorySize, SMEM_B);
    cudaFuncSetAttribute((const void*)tgemm<true,  true,  false, true,  false>,
                         cudaFuncAttributeMaxDynamicSharedMemorySize, SMEM_B);
    cudaFuncSetAttribute((const void*)tgemm<true,  false, true,  false, false>,
                         cudaFuncAttributeMaxDynamicSharedMemorySize, SMEM_B);

    const dim3 blk(256);

    // 1: round x
    round_k<<<(NTOK * H_) / 1024, blk>>>(x, xr);
    // 2,3: transpose qW|kW into wqkt halves
    transpose_k<<<dim3(H_ / 32, H_ / 32, 1), blk>>>(qW, wqkt, H_, H_);
    transpose_k<<<dim3(H_ / 32, H_ / 32, 1), blk>>>(kW, wqkt + (size_t)H_ * H_, H_, H_);
    // 4: transpose vW
    transpose_k<<<dim3(H_ / 32, H_ / 32, 1), blk>>>(vW, wvt, H_, H_);
    // 5: concat q/k biases
    catbias_k<<<(2 * H_) / 256, blk>>>(qb, kb, qkb);

    // 6: fused Q|K projection  [8192, 2048]   <-- ncu captures this launch
    tgemm<true, false, false, true, false><<<dim3(2 * H_ / 256, NTOK / 128, 1), blk, SMEM_B>>>(
        xr, wqkt, qkb, nullptr, qk,
        H_, H_, H_, 2 * H_, 0, 0, 0, 1.0f);

    // 7: V^T = wv^T @ x^T + vb  -> [1024, 8192], rounded
    tgemm<false, false, false, true, true><<<dim3(NTOK / 256, H_ / 128, 1), blk, SMEM_B>>>(
        wvt, xr, vb, nullptr, vt,
        H_, H_, H_, NTOK, 0, 0, 0, 1.0f);

    // 8,9: transpose FFN weights
    transpose_k<<<dim3(F_ / 32, H_ / 32, 1), blk>>>(w1, w1t, H_, F_);
    transpose_k<<<dim3(H_ / 32, F_ / 32, 1), blk>>>(w2, w2t, F_, H_);

    // 10: scores = q @ k^T / sqrt(H), per batch
    tgemm<false, false, false, false, false><<<dim3(S_ / 256, S_ / 128, B_), blk, SMEM_B>>>(
        qk, qk + H_, nullptr, nullptr, sp,
        H_, 2 * H_, 2 * H_, S_,
        (size_t)S_ * 2 * H_, (size_t)S_ * 2 * H_, (size_t)S_ * S_, 0.03125f);

    // 11: softmax (rounded)
    softmax_k<<<NTOK, blk>>>(sp, mask);

    // 12: attn = a @ v, B operand = vt slice per batch
    tgemm<false, false, false, false, false><<<dim3(H_ / 256, S_ / 128, B_), blk, SMEM_B>>>(
        sp, vt, nullptr, nullptr, ap,
        S_, S_, NTOK, H_,
        (size_t)S_ * S_, (size_t)S_, (size_t)S_ * H_, 1.0f);

    // 13: FFN1 h = relu(attn @ w1 + b1), rounded
    tgemm<true, true, false, true, false><<<dim3(F_ / 256, NTOK / 128, 1), blk, SMEM_B>>>(
        ap, w1t, b1, nullptr, hp,
        H_, H_, H_, F_, 0, 0, 0, 1.0f);

    // 14: FFN2 y = attn + h @ w2 + b2
    tgemm<true, false, true, false, false><<<dim3(H_ / 256, NTOK / 128, 1), blk, SMEM_B>>>(
        hp, w2t, b2, ap, yp,
        F_, F_, F_, H_, 0, 0, 0, 1.0f);

    // 15: LayerNorm
    ln_k<<<NTOK, blk>>>(yp, gamma, beta, out);
}

// round 7
// speedup vs baseline: 6.1832x; 1.8474x over previous
#include <cuda_runtime.h>
#include <cuda_fp16.h>
#include <cstdint>
#include <math.h>

#define B_   4
#define S_   2048
#define H_   1024
#define F_   4096
#define NTOK (B_ * S_)   // 8192

// ---------------------------------------------------------------------------
// Scratch (static device globals)
// ---------------------------------------------------------------------------
__device__ __half g_xh[(size_t)NTOK * H_];
__device__ __half g_qk[(size_t)NTOK * 2 * H_];     // [8192, 2048]: q | k
__device__ __half g_s16[(size_t)B_ * S_ * S_];
__device__ __half g_a16[(size_t)NTOK * H_];
__device__ float  g_a32[(size_t)NTOK * H_];
__device__ __half g_h16[(size_t)NTOK * F_];
__device__ float  g_y[(size_t)NTOK * H_];
__device__ __half g_wqkt[(size_t)2 * H_ * H_];     // [2048, 1024]: wq^T | wk^T
__device__ __half g_wvt[(size_t)H_ * H_];
__device__ __half g_w1t[(size_t)H_ * F_];
__device__ __half g_w2t[(size_t)F_ * H_];
__device__ __half g_vt[(size_t)H_ * NTOK];         // [1024, 8192] V^T, all batches
__device__ float  g_qkb[2 * H_];

// ---------------------------------------------------------------------------
// Helpers
// ---------------------------------------------------------------------------
__device__ __forceinline__ uint32_t smem_u32(const void* p) {
    uint32_t a;
    asm("{ .reg .u64 t; cvta.to.shared.u64 t, %1; cvt.u32.u64 %0, t; }" : "=r"(a) : "l"(p));
    return a;
}
__device__ __forceinline__ void cp16(uint32_t s, const void* g) {
    asm volatile("cp.async.cg.shared.global [%0], [%1], 16;" :: "r"(s), "l"(g) : "memory");
}
#define CP_COMMIT() asm volatile("cp.async.commit_group;" ::: "memory")
#define CP_WAIT2()  asm volatile("cp.async.wait_group 2;" ::: "memory")

__device__ __forceinline__ void mma16(float c[4], const uint32_t a[4], const uint32_t b[2]) {
    asm volatile("mma.sync.aligned.m16n8k16.row.col.f32.f16.f16.f32 "
                 "{%0,%1,%2,%3}, {%4,%5,%6,%7}, {%8,%9}, {%0,%1,%2,%3};"
                 : "+f"(c[0]), "+f"(c[1]), "+f"(c[2]), "+f"(c[3])
                 : "r"(a[0]), "r"(a[1]), "r"(a[2]), "r"(a[3]), "r"(b[0]), "r"(b[1]));
}
__device__ __forceinline__ void ldsm4(uint32_t r[4], uint32_t addr) {
    asm volatile("ldmatrix.sync.aligned.m8n8.x4.shared.b16 {%0,%1,%2,%3}, [%4];"
                 : "=r"(r[0]), "=r"(r[1]), "=r"(r[2]), "=r"(r[3]) : "r"(addr));
}

// ---------------------------------------------------------------------------
// FP16 tensor-core GEMM (fp32 accum), cp.async 4-stage pipeline, ldmatrix:
//   acc = alpha * A[M,K] * Bw[N,K]^T (+bias[N]) (+biasM[M]) (+res32) (relu)
//   outputs: C16 (fp16) if O16, C32 (fp32) if O32
// CTA tile 128x256, BK=32, 8 warps (2x4), warp tile 64x64.
// M mult of 128, N mult of 256, K mult of 32. Batched over blockIdx.z.
// Smem/stage: (128+256) rows x 80 B = 30720 B; 4 stages = 122880 B.
// ---------------------------------------------------------------------------
#define ROWB 80                                  // bytes per smem row (32 fp16 + 8 pad)
#define STAGE_B  ((128 + 256) * ROWB)            // 30720
#define NSTAGE 4
#define SMEM_B   (NSTAGE * STAGE_B)              // 122880

template <bool BIAS, bool RELU, bool RES, bool BIASM, bool O16, bool O32>
__global__ __launch_bounds__(256, 1) void tgemm(
    const __half* __restrict__ A, const __half* __restrict__ Bw,
    const float* __restrict__ bias, const float* __restrict__ res,
    __half* __restrict__ C16, float* __restrict__ C32,
    int K, int lda, int ldb, int ldc,
    size_t sA, size_t sB, size_t sC, float alpha)
{
    extern __shared__ uint32_t smem[];
    const uint32_t sbase = smem_u32(smem);

    const int tid  = threadIdx.x;
    const int wid  = tid >> 5, lane = tid & 31;
    const int g    = lane >> 2, t4 = lane & 3;
    const int warpM = wid >> 2, warpN = wid & 3;

    const int z = blockIdx.z;
    A  += (size_t)z * sA;
    Bw += (size_t)z * sB;
    const float* Rp = RES ? (res + (size_t)z * sC) : nullptr;

    const int n0 = blockIdx.x << 8, m0 = blockIdx.y << 7;
    const __half* Ap = A  + (size_t)m0 * lda;
    const __half* Bp = Bw + (size_t)n0 * ldb;

    const int KT = K >> 5;

    auto issue = [&](int kt) {
        const uint32_t s = sbase + (uint32_t)(kt % NSTAGE) * STAGE_B;
        const int kb = kt << 5;
#pragma unroll
        for (int j = 0; j < 2; j++) {            // A: 128 rows x 4 chunks
            const int c = tid + (j << 8);
            const int row = c >> 2, ch = c & 3;
            cp16(s + (uint32_t)(row * ROWB + ch * 16),
                 Ap + (size_t)row * lda + kb + ch * 8);
        }
        const uint32_t sB2 = s + (uint32_t)(128 * ROWB);
#pragma unroll
        for (int j = 0; j < 4; j++) {            // B: 256 rows x 4 chunks
            const int c = tid + (j << 8);
            const int row = c >> 2, ch = c & 3;
            cp16(sB2 + (uint32_t)(row * ROWB + ch * 16),
                 Bp + (size_t)row * ldb + kb + ch * 8);
        }
    };

    // ldmatrix per-lane source offsets (bytes)
    const int aRowOff = (((lane >> 3) & 1) << 3) + (lane & 7);
    const int aKb     = (lane >> 4) << 4;                 // 0 or 16 bytes
    const int bRowOff = ((lane >> 4) << 3) + (lane & 7);
    const int bKb     = ((lane >> 3) & 1) << 4;

    const uint32_t aLane = sbase + (uint32_t)((warpM * 64 + aRowOff) * ROWB + aKb);
    const uint32_t bLane = sbase + (uint32_t)(128 * ROWB)
        + (uint32_t)((warpN * 64 + bRowOff) * ROWB + bKb);

    float acc[4][8][4];
#pragma unroll
    for (int mt = 0; mt < 4; mt++)
#pragma unroll
        for (int nt = 0; nt < 8; nt++)
#pragma unroll
            for (int i = 0; i < 4; i++) acc[mt][nt][i] = 0.0f;

    issue(0); CP_COMMIT();
    if (KT > 1) issue(1);
    CP_COMMIT();
    if (KT > 2) issue(2);
    CP_COMMIT();

    for (int kt = 0; kt < KT; kt++) {
        CP_WAIT2();
        __syncthreads();

        if (kt + 3 < KT) issue(kt + 3);
        CP_COMMIT();

        const uint32_t stOff = (uint32_t)((kt % NSTAGE) * STAGE_B);

#pragma unroll
        for (int ks = 0; ks < 2; ks++) {         // two k16 chunks per BK=32
            uint32_t afr[4][4], bfr[8][2];
#pragma unroll
            for (int mt = 0; mt < 4; mt++)
                ldsm4(afr[mt], aLane + stOff + (uint32_t)(mt * 16 * ROWB + ks * 32));
#pragma unroll
            for (int p = 0; p < 4; p++) {
                uint32_t r[4];
                ldsm4(r, bLane + stOff + (uint32_t)(p * 16 * ROWB + ks * 32));
                bfr[2 * p][0] = r[0]; bfr[2 * p][1] = r[1];
                bfr[2 * p + 1][0] = r[2]; bfr[2 * p + 1][1] = r[3];
            }
#pragma unroll
            for (int mt = 0; mt < 4; mt++)
#pragma unroll
                for (int nt = 0; nt < 8; nt++)
                    mma16(acc[mt][nt], afr[mt], bfr[nt]);
        }
    }

    // --- fused epilogue ---
    __half* Cp16 = O16 ? (C16 + (size_t)z * sC) : nullptr;
    float*  Cp32 = O32 ? (C32 + (size_t)z * sC) : nullptr;
    const int rbase = m0 + warpM * 64;
    const int cbase = n0 + warpN * 64;
#pragma unroll
    for (int mt = 0; mt < 4; mt++) {
#pragma unroll
        for (int nt = 0; nt < 8; nt++) {
            const int col = cbase + nt * 8 + (t4 << 1);
            float bx = 0.f, by = 0.f;
            if (BIAS) {
                float2 bb = *(const float2*)(bias + col);
                bx = bb.x; by = bb.y;
            }
#pragma unroll
            for (int hh = 0; hh < 2; hh++) {
                const int row = rbase + mt * 16 + g + hh * 8;
                float v0 = acc[mt][nt][hh * 2 + 0] * alpha;
                float v1 = acc[mt][nt][hh * 2 + 1] * alpha;
                if (BIAS) { v0 += bx; v1 += by; }
                if (BIASM) { const float bm = bias[row]; v0 += bm; v1 += bm; }
                if (RES) {
                    float2 rr = *(const float2*)(Rp + (size_t)row * ldc + col);
                    v0 += rr.x; v1 += rr.y;
                }
                if (RELU) { v0 = fmaxf(v0, 0.f); v1 = fmaxf(v1, 0.f); }
                if (O16)
                    *(__half2*)(Cp16 + (size_t)row * ldc + col) = __floats2half2_rn(v0, v1);
                if (O32) {
                    float2 o; o.x = v0; o.y = v1;
                    *(float2*)(Cp32 + (size_t)row * ldc + col) = o;
                }
            }
        }
    }
}

// ---------------------------------------------------------------------------
// x (fp32) -> fp16
// ---------------------------------------------------------------------------
__global__ __launch_bounds__(256) void tohalf_k(const float* __restrict__ in,
                                                __half* __restrict__ out)
{
    const size_t i = ((size_t)blockIdx.x * 256 + threadIdx.x) * 4;
    float4 v = *(const float4*)(in + i);
    __half2* o = (__half2*)(out + i);
    o[0] = __floats2half2_rn(v.x, v.y);
    o[1] = __floats2half2_rn(v.z, v.w);
}

// ---------------------------------------------------------------------------
// Concat two H_-vectors (bias) into one 2H_ vector
// ---------------------------------------------------------------------------
__global__ __launch_bounds__(256) void catbias_k(const float* __restrict__ a,
                                                 const float* __restrict__ b,
                                                 float* __restrict__ out)
{
    const int i = blockIdx.x * 256 + threadIdx.x;
    out[i] = (i < H_) ? a[i] : b[i - H_];
}

// ---------------------------------------------------------------------------
// Transpose fp32 src [R,C] -> fp16 dst [C,R]
// ---------------------------------------------------------------------------
__global__ __launch_bounds__(256) void transpose_k(const float* __restrict__ src,
                                                   __half* __restrict__ dst, int R, int C)
{
    __shared__ float t[32][33];
    const int bx = blockIdx.x << 5, by = blockIdx.y << 5;
    const int tx = threadIdx.x & 31, ty = (threadIdx.x >> 5) << 2;
#pragma unroll
    for (int j = 0; j < 4; j++)
        t[ty + j][tx] = src[(size_t)(by + ty + j) * C + bx + tx];
    __syncthreads();
#pragma unroll
    for (int j = 0; j < 4; j++)
        dst[(size_t)(bx + ty + j) * R + by + tx] = __float2half_rn(t[tx][ty + j]);
}

// ---------------------------------------------------------------------------
// Row softmax (S_ wide) on fp16 scores with fp32 mask; in-place fp16
// ---------------------------------------------------------------------------
__global__ __launch_bounds__(256) void softmax_k(__half* __restrict__ s,
                                                 const float* __restrict__ mask)
{
    const int row = blockIdx.x;
    const int q   = row & (S_ - 1);
    __half2* p = (__half2*)(s + (size_t)row * S_);
    const float* mrow = mask + (size_t)q * S_;
    const int tid = threadIdx.x;
    __shared__ float red[256];

    float vals[8];
    float vmax = -3.0e38f;
#pragma unroll
    for (int i = 0; i < 4; i++) {
        const int idx = tid + i * 256;          // half2 index
        const float2 v2 = __half22float2(p[idx]);
        const float m0 = mrow[idx * 2], m1 = mrow[idx * 2 + 1];
        const float a = v2.x + m0, b = v2.y + m1;
        vals[2 * i] = a; vals[2 * i + 1] = b;
        vmax = fmaxf(vmax, fmaxf(a, b));
    }
    red[tid] = vmax; __syncthreads();
    for (int o = 128; o > 0; o >>= 1) {
        if (tid < o) red[tid] = fmaxf(red[tid], red[tid + o]);
        __syncthreads();
    }
    vmax = red[0]; __syncthreads();
    float sum = 0.0f;
#pragma unroll
    for (int i = 0; i < 8; i++) { const float e = __expf(vals[i] - vmax); vals[i] = e; sum += e; }
    red[tid] = sum; __syncthreads();
    for (int o = 128; o > 0; o >>= 1) {
        if (tid < o) red[tid] += red[tid + o];
        __syncthreads();
    }
    const float inv = 1.0f / red[0];
#pragma unroll
    for (int i = 0; i < 4; i++)
        p[tid + i * 256] = __floats2half2_rn(vals[2 * i] * inv, vals[2 * i + 1] * inv);
}

// ---------------------------------------------------------------------------
// LayerNorm (H_=1024)
// ---------------------------------------------------------------------------
__global__ __launch_bounds__(256) void ln_k(const float* __restrict__ y,
                                            const float* __restrict__ gamma,
                                            const float* __restrict__ beta,
                                            float* __restrict__ out)
{
    const int row = blockIdx.x;
    const float4* p4 = (const float4*)(y + (size_t)row * H_);
    const int tid = threadIdx.x;
    __shared__ float rs[256], rq[256];

    const float4 v = p4[tid];
    rs[tid] = v.x + v.y + v.z + v.w;
    rq[tid] = v.x * v.x + v.y * v.y + v.z * v.z + v.w * v.w;
    __syncthreads();
    for (int o = 128; o > 0; o >>= 1) {
        if (tid < o) { rs[tid] += rs[tid + o]; rq[tid] += rq[tid + o]; }
        __syncthreads();
    }
    const float mu  = rs[0] * (1.0f / H_);
    const float var = rq[0] * (1.0f / H_) - mu * mu;
    const float inv = rsqrtf(var + 1e-5f);
    const float4 g = ((const float4*)gamma)[tid];
    const float4 b = ((const float4*)beta)[tid];
    float4 o;
    o.x = (v.x - mu) * inv * g.x + b.x;
    o.y = (v.y - mu) * inv * g.y + b.y;
    o.z = (v.z - mu) * inv * g.z + b.z;
    o.w = (v.w - mu) * inv * g.w + b.w;
    ((float4*)(out + (size_t)row * H_))[tid] = o;
}

// ---------------------------------------------------------------------------
// Launch
// ---------------------------------------------------------------------------
extern "C" void kernel_launch(void* const* d_in, const int* in_sizes, int n_in,
                              void* d_out, int out_size)
{
    const float* x     = (const float*)d_in[0];
    const float* mask  = (const float*)d_in[1];
    const float* qW    = (const float*)d_in[2];
    const float* qb    = (const float*)d_in[3];
    const float* kW    = (const float*)d_in[4];
    const float* kb    = (const float*)d_in[5];
    const float* vW    = (const float*)d_in[6];
    const float* vb    = (const float*)d_in[7];
    const float* w1    = (const float*)d_in[8];
    const float* b1    = (const float*)d_in[9];
    const float* w2    = (const float*)d_in[10];
    const float* b2    = (const float*)d_in[11];
    const float* gamma = (const float*)d_in[12];
    const float* beta  = (const float*)d_in[13];
    float* out = (float*)d_out;

    __half *xh, *qk, *s16, *a16, *h16, *wqkt, *wvt, *w1t, *w2t, *vt;
    float *a32, *yp, *qkb;
    cudaGetSymbolAddress((void**)&xh, g_xh);
    cudaGetSymbolAddress((void**)&qk, g_qk);
    cudaGetSymbolAddress((void**)&s16, g_s16);
    cudaGetSymbolAddress((void**)&a16, g_a16);
    cudaGetSymbolAddress((void**)&a32, g_a32);
    cudaGetSymbolAddress((void**)&h16, g_h16);
    cudaGetSymbolAddress((void**)&yp, g_y);
    cudaGetSymbolAddress((void**)&wqkt, g_wqkt);
    cudaGetSymbolAddress((void**)&wvt, g_wvt);
    cudaGetSymbolAddress((void**)&w1t, g_w1t);
    cudaGetSymbolAddress((void**)&w2t, g_w2t);
    cudaGetSymbolAddress((void**)&vt, g_vt);
    cudaGetSymbolAddress((void**)&qkb, g_qkb);

    // Template instances used:
    //  QK:    <BIAS,0,0,0, O16=1,O32=0>
    //  V^T:   <0,0,0,BIASM=1, 1,0>
    //  score: <0,0,0,0, 1,0>
    //  attn:  <0,0,0,0, 1,1>
    //  FFN1:  <1,RELU=1,0,0, 1,0>
    //  FFN2:  <1,0,RES=1,0, 0,1>
    cudaFuncSetAttribute((const void*)tgemm<true,  false, false, false, true,  false>,
                         cudaFuncAttributeMaxDynamicSharedMemorySize, SMEM_B);
    cudaFuncSetAttribute((const void*)tgemm<false, false, false, true,  true,  false>,
                         cudaFuncAttributeMaxDynamicSharedMemorySize, SMEM_B);
    cudaFuncSetAttribute((const void*)tgemm<false, false, false, false, true,  false>,
                         cudaFuncAttributeMaxDynamicSharedMemorySize, SMEM_B);
    cudaFuncSetAttribute((const void*)tgemm<false, false, false, false, true,  true >,
                         cudaFuncAttributeMaxDynamicSharedMemorySize, SMEM_B);
    cudaFuncSetAttribute((const void*)tgemm<true,  true,  false, false, true,  false>,
                         cudaFuncAttributeMaxDynamicSharedMemorySize, SMEM_B);
    cudaFuncSetAttribute((const void*)tgemm<true,  false, true,  false, false, true >,
                         cudaFuncAttributeMaxDynamicSharedMemorySize, SMEM_B);

    const dim3 blk(256);

    // convert x; transpose weights to fp16 [N,K]
    tohalf_k<<<(NTOK * H_) / 1024, blk>>>(x, xh);
    transpose_k<<<dim3(H_ / 32, H_ / 32, 1), blk>>>(qW, wqkt, H_, H_);
    transpose_k<<<dim3(H_ / 32, H_ / 32, 1), blk>>>(kW, wqkt + (size_t)H_ * H_, H_, H_);
    transpose_k<<<dim3(H_ / 32, H_ / 32, 1), blk>>>(vW, wvt, H_, H_);
    transpose_k<<<dim3(F_ / 32, H_ / 32, 1), blk>>>(w1, w1t, H_, F_);
    transpose_k<<<dim3(H_ / 32, F_ / 32, 1), blk>>>(w2, w2t, F_, H_);
    catbias_k<<<(2 * H_) / 256, blk>>>(qb, kb, qkb);

    // fused Q|K projection -> qk fp16 [8192, 2048]
    tgemm<true, false, false, false, true, false>
        <<<dim3(2 * H_ / 256, NTOK / 128, 1), blk, SMEM_B>>>(
        xh, wqkt, qkb, nullptr, qk, nullptr,
        H_, H_, H_, 2 * H_, 0, 0, 0, 1.0f);

    // V^T = wv^T @ x^T + vb -> vt fp16 [1024, 8192]
    tgemm<false, false, false, true, true, false>
        <<<dim3(NTOK / 256, H_ / 128, 1), blk, SMEM_B>>>(
        wvt, xh, vb, nullptr, vt, nullptr,
        H_, H_, H_, NTOK, 0, 0, 0, 1.0f);

    // scores = q @ k^T / sqrt(H) -> s16, per batch
    tgemm<false, false, false, false, true, false>
        <<<dim3(S_ / 256, S_ / 128, B_), blk, SMEM_B>>>(
        qk, qk + H_, nullptr, nullptr, s16, nullptr,
        H_, 2 * H_, 2 * H_, S_,
        (size_t)S_ * 2 * H_, (size_t)S_ * 2 * H_, (size_t)S_ * S_, 0.03125f);

    // softmax in place on fp16
    softmax_k<<<NTOK, blk>>>(s16, mask);

    // attn = a @ v -> a16 (fp16) + a32 (fp32), per batch
    tgemm<false, false, false, false, true, true>
        <<<dim3(H_ / 256, S_ / 128, B_), blk, SMEM_B>>>(
        s16, vt, nullptr, nullptr, a16, a32,
        S_, S_, NTOK, H_,
        (size_t)S_ * S_, (size_t)S_, (size_t)S_ * H_, 1.0f);

    // FFN1: h = relu(attn @ w1 + b1) -> h16
    tgemm<true, true, false, false, true, false>
        <<<dim3(F_ / 256, NTOK / 128, 1), blk, SMEM_B>>>(
        a16, w1t, b1, nullptr, h16, nullptr,
        H_, H_, H_, F_, 0, 0, 0, 1.0f);

    // FFN2: y = attn32 + h @ w2 + b2 -> fp32
    tgemm<true, false, true, false, false, true>
        <<<dim3(H_ / 256, NTOK / 128, 1), blk, SMEM_B>>>(
        h16, w2t, b2, a32, nullptr, yp,
        F_, F_, F_, H_, 0, 0, 0, 1.0f);

    // LayerNorm
    ln_k<<<NTOK, blk>>>(yp, gamma, beta, out);
}

// round 8
// speedup vs baseline: 7.7235x; 1.2491x over previous
#include <cuda_runtime.h>
#include <cuda_fp16.h>
#include <cstdint>
#include <math.h>

#define B_   4
#define S_   2048
#define H_   1024
#define F_   4096
#define NTOK (B_ * S_)   // 8192

// ---------------------------------------------------------------------------
// Scratch (static device globals)
// ---------------------------------------------------------------------------
__device__ __half g_xh[(size_t)NTOK * H_];
__device__ __half g_qk[(size_t)NTOK * 2 * H_];     // [8192, 2048]: q | k
__device__ __half g_s16[(size_t)B_ * S_ * S_];
__device__ __half g_a16[(size_t)NTOK * H_];
__device__ float  g_a32[(size_t)NTOK * H_];
__device__ __half g_h16[(size_t)NTOK * F_];
__device__ float  g_y[(size_t)NTOK * H_];
__device__ __half g_wqkt[(size_t)2 * H_ * H_];     // [2048, 1024]: wq^T | wk^T
__device__ __half g_wvt[(size_t)H_ * H_];
__device__ __half g_w1t[(size_t)H_ * F_];
__device__ __half g_w2t[(size_t)F_ * H_];
__device__ __half g_vt[(size_t)H_ * NTOK];         // [1024, 8192] V^T, all batches
__device__ float  g_qkb[2 * H_];

// ---------------------------------------------------------------------------
// Helpers
// ---------------------------------------------------------------------------
__device__ __forceinline__ uint32_t smem_u32(const void* p) {
    uint32_t a;
    asm("{ .reg .u64 t; cvta.to.shared.u64 t, %1; cvt.u32.u64 %0, t; }" : "=r"(a) : "l"(p));
    return a;
}
__device__ __forceinline__ void cp16(uint32_t s, const void* g) {
    asm volatile("cp.async.cg.shared.global [%0], [%1], 16;" :: "r"(s), "l"(g) : "memory");
}
#define CP_COMMIT() asm volatile("cp.async.commit_group;" ::: "memory")
#define CP_WAIT2()  asm volatile("cp.async.wait_group 2;" ::: "memory")

__device__ __forceinline__ void mma16(float c[4], const uint32_t a[4], const uint32_t b[2]) {
    asm volatile("mma.sync.aligned.m16n8k16.row.col.f32.f16.f16.f32 "
                 "{%0,%1,%2,%3}, {%4,%5,%6,%7}, {%8,%9}, {%0,%1,%2,%3};"
                 : "+f"(c[0]), "+f"(c[1]), "+f"(c[2]), "+f"(c[3])
                 : "r"(a[0]), "r"(a[1]), "r"(a[2]), "r"(a[3]), "r"(b[0]), "r"(b[1]));
}
__device__ __forceinline__ void ldsm4(uint32_t r[4], uint32_t addr) {
    asm volatile("ldmatrix.sync.aligned.m8n8.x4.shared.b16 {%0,%1,%2,%3}, [%4];"
                 : "=r"(r[0]), "=r"(r[1]), "=r"(r[2]), "=r"(r[3]) : "r"(addr));
}

// ---------------------------------------------------------------------------
// FP16 tensor-core GEMM (fp32 accum), cp.async 4-stage pipeline, ldmatrix:
//   acc = alpha * A[M,K] * Bw[N,K]^T (+bias[N]) (+biasM[M]) (+res32) (relu)
//   outputs: C16 (fp16) if O16, C32 (fp32) if O32
// CTA tile 128x128, BK=32, 4 warps (2x2), warp tile 64x64, 128 threads.
// 2 CTAs/SM target. M,N mult of 128, K mult of 32. Batched over blockIdx.z.
// Smem/stage: (128+128) rows x 80 B = 20480 B; 4 stages = 81920 B.
// ---------------------------------------------------------------------------
#define ROWB 80                                  // bytes per smem row (32 fp16 + 8 pad)
#define STAGE_B  ((128 + 128) * ROWB)            // 20480
#define NSTAGE 4
#define SMEM_B   (NSTAGE * STAGE_B)              // 81920

template <bool BIAS, bool RELU, bool RES, bool BIASM, bool O16, bool O32>
__global__ __launch_bounds__(128, 2) void tgemm(
    const __half* __restrict__ A, const __half* __restrict__ Bw,
    const float* __restrict__ bias, const float* __restrict__ res,
    __half* __restrict__ C16, float* __restrict__ C32,
    int K, int lda, int ldb, int ldc,
    size_t sA, size_t sB, size_t sC, float alpha)
{
    extern __shared__ uint32_t smem[];
    const uint32_t sbase = smem_u32(smem);

    const int tid  = threadIdx.x;
    const int wid  = tid >> 5, lane = tid & 31;
    const int g    = lane >> 2, t4 = lane & 3;
    const int warpM = wid >> 1, warpN = wid & 1;

    const int z = blockIdx.z;
    A  += (size_t)z * sA;
    Bw += (size_t)z * sB;
    const float* Rp = RES ? (res + (size_t)z * sC) : nullptr;

    const int n0 = blockIdx.x << 7, m0 = blockIdx.y << 7;
    const __half* Ap = A  + (size_t)m0 * lda;
    const __half* Bp = Bw + (size_t)n0 * ldb;

    const int KT = K >> 5;

    auto issue = [&](int kt) {
        const uint32_t s = sbase + (uint32_t)(kt % NSTAGE) * STAGE_B;
        const int kb = kt << 5;
#pragma unroll
        for (int j = 0; j < 4; j++) {            // A: 128 rows x 4 chunks = 512
            const int c = tid + (j << 7);
            const int row = c >> 2, ch = c & 3;
            cp16(s + (uint32_t)(row * ROWB + ch * 16),
                 Ap + (size_t)row * lda + kb + ch * 8);
        }
        const uint32_t sB2 = s + (uint32_t)(128 * ROWB);
#pragma unroll
        for (int j = 0; j < 4; j++) {            // B: 128 rows x 4 chunks = 512
            const int c = tid + (j << 7);
            const int row = c >> 2, ch = c & 3;
            cp16(sB2 + (uint32_t)(row * ROWB + ch * 16),
                 Bp + (size_t)row * ldb + kb + ch * 8);
        }
    };

    // ldmatrix per-lane source offsets (bytes)
    const int aRowOff = (((lane >> 3) & 1) << 3) + (lane & 7);
    const int aKb     = (lane >> 4) << 4;                 // 0 or 16 bytes
    const int bRowOff = ((lane >> 4) << 3) + (lane & 7);
    const int bKb     = ((lane >> 3) & 1) << 4;

    const uint32_t aLane = sbase + (uint32_t)((warpM * 64 + aRowOff) * ROWB + aKb);
    const uint32_t bLane = sbase + (uint32_t)(128 * ROWB)
        + (uint32_t)((warpN * 64 + bRowOff) * ROWB + bKb);

    float acc[4][8][4];
#pragma unroll
    for (int mt = 0; mt < 4; mt++)
#pragma unroll
        for (int nt = 0; nt < 8; nt++)
#pragma unroll
            for (int i = 0; i < 4; i++) acc[mt][nt][i] = 0.0f;

    issue(0); CP_COMMIT();
    if (KT > 1) issue(1);
    CP_COMMIT();
    if (KT > 2) issue(2);
    CP_COMMIT();

    for (int kt = 0; kt < KT; kt++) {
        CP_WAIT2();
        __syncthreads();

        if (kt + 3 < KT) issue(kt + 3);
        CP_COMMIT();

        const uint32_t stOff = (uint32_t)((kt % NSTAGE) * STAGE_B);

#pragma unroll
        for (int ks = 0; ks < 2; ks++) {         // two k16 chunks per BK=32
            uint32_t afr[4][4], bfr[8][2];
#pragma unroll
            for (int mt = 0; mt < 4; mt++)
                ldsm4(afr[mt], aLane + stOff + (uint32_t)(mt * 16 * ROWB + ks * 32));
#pragma unroll
            for (int p = 0; p < 4; p++) {
                uint32_t r[4];
                ldsm4(r, bLane + stOff + (uint32_t)(p * 16 * ROWB + ks * 32));
                bfr[2 * p][0] = r[0]; bfr[2 * p][1] = r[1];
                bfr[2 * p + 1][0] = r[2]; bfr[2 * p + 1][1] = r[3];
            }
#pragma unroll
            for (int mt = 0; mt < 4; mt++)
#pragma unroll
                for (int nt = 0; nt < 8; nt++)
                    mma16(acc[mt][nt], afr[mt], bfr[nt]);
        }
    }

    // --- fused epilogue ---
    __half* Cp16 = O16 ? (C16 + (size_t)z * sC) : nullptr;
    float*  Cp32 = O32 ? (C32 + (size_t)z * sC) : nullptr;
    const int rbase = m0 + warpM * 64;
    const int cbase = n0 + warpN * 64;
#pragma unroll
    for (int mt = 0; mt < 4; mt++) {
#pragma unroll
        for (int nt = 0; nt < 8; nt++) {
            const int col = cbase + nt * 8 + (t4 << 1);
            float bx = 0.f, by = 0.f;
            if (BIAS) {
                float2 bb = *(const float2*)(bias + col);
                bx = bb.x; by = bb.y;
            }
#pragma unroll
            for (int hh = 0; hh < 2; hh++) {
                const int row = rbase + mt * 16 + g + hh * 8;
                float v0 = acc[mt][nt][hh * 2 + 0] * alpha;
                float v1 = acc[mt][nt][hh * 2 + 1] * alpha;
                if (BIAS) { v0 += bx; v1 += by; }
                if (BIASM) { const float bm = bias[row]; v0 += bm; v1 += bm; }
                if (RES) {
                    float2 rr = *(const float2*)(Rp + (size_t)row * ldc + col);
                    v0 += rr.x; v1 += rr.y;
                }
                if (RELU) { v0 = fmaxf(v0, 0.f); v1 = fmaxf(v1, 0.f); }
                if (O16)
                    *(__half2*)(Cp16 + (size_t)row * ldc + col) = __floats2half2_rn(v0, v1);
                if (O32) {
                    float2 o; o.x = v0; o.y = v1;
                    *(float2*)(Cp32 + (size_t)row * ldc + col) = o;
                }
            }
        }
    }
}

// ---------------------------------------------------------------------------
// x (fp32) -> fp16
// ---------------------------------------------------------------------------
__global__ __launch_bounds__(256) void tohalf_k(const float* __restrict__ in,
                                                __half* __restrict__ out)
{
    const size_t i = ((size_t)blockIdx.x * 256 + threadIdx.x) * 4;
    float4 v = *(const float4*)(in + i);
    __half2* o = (__half2*)(out + i);
    o[0] = __floats2half2_rn(v.x, v.y);
    o[1] = __floats2half2_rn(v.z, v.w);
}

// ---------------------------------------------------------------------------
// Concat two H_-vectors (bias) into one 2H_ vector
// ---------------------------------------------------------------------------
__global__ __launch_bounds__(256) void catbias_k(const float* __restrict__ a,
                                                 const float* __restrict__ b,
                                                 float* __restrict__ out)
{
    const int i = blockIdx.x * 256 + threadIdx.x;
    out[i] = (i < H_) ? a[i] : b[i - H_];
}

// ---------------------------------------------------------------------------
// Transpose fp32 src [R,C] -> fp16 dst [C,R]
// ---------------------------------------------------------------------------
__global__ __launch_bounds__(256) void transpose_k(const float* __restrict__ src,
                                                   __half* __restrict__ dst, int R, int C)
{
    __shared__ float t[32][33];
    const int bx = blockIdx.x << 5, by = blockIdx.y << 5;
    const int tx = threadIdx.x & 31, ty = (threadIdx.x >> 5) << 2;
#pragma unroll
    for (int j = 0; j < 4; j++)
        t[ty + j][tx] = src[(size_t)(by + ty + j) * C + bx + tx];
    __syncthreads();
#pragma unroll
    for (int j = 0; j < 4; j++)
        dst[(size_t)(bx + ty + j) * R + by + tx] = __float2half_rn(t[tx][ty + j]);
}

// ---------------------------------------------------------------------------
// Row softmax (S_ wide) on fp16 scores with fp32 mask; in-place fp16
// ---------------------------------------------------------------------------
__global__ __launch_bounds__(256) void softmax_k(__half* __restrict__ s,
                                                 const float* __restrict__ mask)
{
    const int row = blockIdx.x;
    const int q   = row & (S_ - 1);
    __half2* p = (__half2*)(s + (size_t)row * S_);
    const float* mrow = mask + (size_t)q * S_;
    const int tid = threadIdx.x;
    __shared__ float red[256];

    float vals[8];
    float vmax = -3.0e38f;
#pragma unroll
    for (int i = 0; i < 4; i++) {
        const int idx = tid + i * 256;          // half2 index
        const float2 v2 = __half22float2(p[idx]);
        const float m0 = mrow[idx * 2], m1 = mrow[idx * 2 + 1];
        const float a = v2.x + m0, b = v2.y + m1;
        vals[2 * i] = a; vals[2 * i + 1] = b;
        vmax = fmaxf(vmax, fmaxf(a, b));
    }
    red[tid] = vmax; __syncthreads();
    for (int o = 128; o > 0; o >>= 1) {
        if (tid < o) red[tid] = fmaxf(red[tid], red[tid + o]);
        __syncthreads();
    }
    vmax = red[0]; __syncthreads();
    float sum = 0.0f;
#pragma unroll
    for (int i = 0; i < 8; i++) { const float e = __expf(vals[i] - vmax); vals[i] = e; sum += e; }
    red[tid] = sum; __syncthreads();
    for (int o = 128; o > 0; o >>= 1) {
        if (tid < o) red[tid] += red[tid + o];
        __syncthreads();
    }
    const float inv = 1.0f / red[0];
#pragma unroll
    for (int i = 0; i < 4; i++)
        p[tid + i * 256] = __floats2half2_rn(vals[2 * i] * inv, vals[2 * i + 1] * inv);
}

// ---------------------------------------------------------------------------
// LayerNorm (H_=1024)
// ---------------------------------------------------------------------------
__global__ __launch_bounds__(256) void ln_k(const float* __restrict__ y,
                                            const float* __restrict__ gamma,
                                            const float* __restrict__ beta,
                                            float* __restrict__ out)
{
    const int row = blockIdx.x;
    const float4* p4 = (const float4*)(y + (size_t)row * H_);
    const int tid = threadIdx.x;
    __shared__ float rs[256], rq[256];

    const float4 v = p4[tid];
    rs[tid] = v.x + v.y + v.z + v.w;
    rq[tid] = v.x * v.x + v.y * v.y + v.z * v.z + v.w * v.w;
    __syncthreads();
    for (int o = 128; o > 0; o >>= 1) {
        if (tid < o) { rs[tid] += rs[tid + o]; rq[tid] += rq[tid + o]; }
        __syncthreads();
    }
    const float mu  = rs[0] * (1.0f / H_);
    const float var = rq[0] * (1.0f / H_) - mu * mu;
    const float inv = rsqrtf(var + 1e-5f);
    const float4 g = ((const float4*)gamma)[tid];
    const float4 b = ((const float4*)beta)[tid];
    float4 o;
    o.x = (v.x - mu) * inv * g.x + b.x;
    o.y = (v.y - mu) * inv * g.y + b.y;
    o.z = (v.z - mu) * inv * g.z + b.z;
    o.w = (v.w - mu) * inv * g.w + b.w;
    ((float4*)(out + (size_t)row * H_))[tid] = o;
}

// ---------------------------------------------------------------------------
// Launch
// ---------------------------------------------------------------------------
extern "C" void kernel_launch(void* const* d_in, const int* in_sizes, int n_in,
                              void* d_out, int out_size)
{
    const float* x     = (const float*)d_in[0];
    const float* mask  = (const float*)d_in[1];
    const float* qW    = (const float*)d_in[2];
    const float* qb    = (const float*)d_in[3];
    const float* kW    = (const float*)d_in[4];
    const float* kb    = (const float*)d_in[5];
    const float* vW    = (const float*)d_in[6];
    const float* vb    = (const float*)d_in[7];
    const float* w1    = (const float*)d_in[8];
    const float* b1    = (const float*)d_in[9];
    const float* w2    = (const float*)d_in[10];
    const float* b2    = (const float*)d_in[11];
    const float* gamma = (const float*)d_in[12];
    const float* beta  = (const float*)d_in[13];
    float* out = (float*)d_out;

    __half *xh, *qk, *s16, *a16, *h16, *wqkt, *wvt, *w1t, *w2t, *vt;
    float *a32, *yp, *qkb;
    cudaGetSymbolAddress((void**)&xh, g_xh);
    cudaGetSymbolAddress((void**)&qk, g_qk);
    cudaGetSymbolAddress((void**)&s16, g_s16);
    cudaGetSymbolAddress((void**)&a16, g_a16);
    cudaGetSymbolAddress((void**)&a32, g_a32);
    cudaGetSymbolAddress((void**)&h16, g_h16);
    cudaGetSymbolAddress((void**)&yp, g_y);
    cudaGetSymbolAddress((void**)&wqkt, g_wqkt);
    cudaGetSymbolAddress((void**)&wvt, g_wvt);
    cudaGetSymbolAddress((void**)&w1t, g_w1t);
    cudaGetSymbolAddress((void**)&w2t, g_w2t);
    cudaGetSymbolAddress((void**)&vt, g_vt);
    cudaGetSymbolAddress((void**)&qkb, g_qkb);

    cudaFuncSetAttribute((const void*)tgemm<true,  false, false, false, true,  false>,
                         cudaFuncAttributeMaxDynamicSharedMemorySize, SMEM_B);
    cudaFuncSetAttribute((const void*)tgemm<false, false, false, true,  true,  false>,
                         cudaFuncAttributeMaxDynamicSharedMemorySize, SMEM_B);
    cudaFuncSetAttribute((const void*)tgemm<false, false, false, false, true,  false>,
                         cudaFuncAttributeMaxDynamicSharedMemorySize, SMEM_B);
    cudaFuncSetAttribute((const void*)tgemm<false, false, false, false, true,  true >,
                         cudaFuncAttributeMaxDynamicSharedMemorySize, SMEM_B);
    cudaFuncSetAttribute((const void*)tgemm<true,  true,  false, false, true,  false>,
                         cudaFuncAttributeMaxDynamicSharedMemorySize, SMEM_B);
    cudaFuncSetAttribute((const void*)tgemm<true,  false, true,  false, false, true >,
                         cudaFuncAttributeMaxDynamicSharedMemorySize, SMEM_B);

    const dim3 blk(256);
    const dim3 gblk(128);

    // Launches 1-5 (prep), so launch 6 (ncu -s 5 -c 1 capture) is the QK GEMM.
    tohalf_k<<<(NTOK * H_) / 1024, blk>>>(x, xh);                                   // 1
    transpose_k<<<dim3(H_ / 32, H_ / 32, 1), blk>>>(qW, wqkt, H_, H_);              // 2
    transpose_k<<<dim3(H_ / 32, H_ / 32, 1), blk>>>(kW, wqkt + (size_t)H_ * H_, H_, H_); // 3
    transpose_k<<<dim3(H_ / 32, H_ / 32, 1), blk>>>(vW, wvt, H_, H_);               // 4
    catbias_k<<<(2 * H_) / 256, blk>>>(qb, kb, qkb);                                // 5

    // 6: fused Q|K projection -> qk fp16 [8192, 2048]   <-- ncu capture
    tgemm<true, false, false, false, true, false>
        <<<dim3(2 * H_ / 128, NTOK / 128, 1), gblk, SMEM_B>>>(
        xh, wqkt, qkb, nullptr, qk, nullptr,
        H_, H_, H_, 2 * H_, 0, 0, 0, 1.0f);

    // 7: V^T = wv^T @ x^T + vb -> vt fp16 [1024, 8192]
    tgemm<false, false, false, true, true, false>
        <<<dim3(NTOK / 128, H_ / 128, 1), gblk, SMEM_B>>>(
        wvt, xh, vb, nullptr, vt, nullptr,
        H_, H_, H_, NTOK, 0, 0, 0, 1.0f);

    // 8,9: FFN weight transposes (needed only from launch 13)
    transpose_k<<<dim3(F_ / 32, H_ / 32, 1), blk>>>(w1, w1t, H_, F_);
    transpose_k<<<dim3(H_ / 32, F_ / 32, 1), blk>>>(w2, w2t, F_, H_);

    // 10: scores = q @ k^T / sqrt(H) -> s16, per batch
    tgemm<false, false, false, false, true, false>
        <<<dim3(S_ / 128, S_ / 128, B_), gblk, SMEM_B>>>(
        qk, qk + H_, nullptr, nullptr, s16, nullptr,
        H_, 2 * H_, 2 * H_, S_,
        (size_t)S_ * 2 * H_, (size_t)S_ * 2 * H_, (size_t)S_ * S_, 0.03125f);

    // 11: softmax in place on fp16
    softmax_k<<<NTOK, blk>>>(s16, mask);

    // 12: attn = a @ v -> a16 (fp16) + a32 (fp32), per batch
    tgemm<false, false, false, false, true, true>
        <<<dim3(H_ / 128, S_ / 128, B_), gblk, SMEM_B>>>(
        s16, vt, nullptr, nullptr, a16, a32,
        S_, S_, NTOK, H_,
        (size_t)S_ * S_, (size_t)S_, (size_t)S_ * H_, 1.0f);

    // 13: FFN1: h = relu(attn @ w1 + b1) -> h16
    tgemm<true, true, false, false, true, false>
        <<<dim3(F_ / 128, NTOK / 128, 1), gblk, SMEM_B>>>(
        a16, w1t, b1, nullptr, h16, nullptr,
        H_, H_, H_, F_, 0, 0, 0, 1.0f);

    // 14: FFN2: y = attn32 + h @ w2 + b2 -> fp32
    tgemm<true, false, true, false, false, true>
        <<<dim3(H_ / 128, NTOK / 128, 1), gblk, SMEM_B>>>(
        h16, w2t, b2, a32, nullptr, yp,
        F_, F_, F_, H_, 0, 0, 0, 1.0f);

    // 15: LayerNorm
    ln_k<<<NTOK, blk>>>(yp, gamma, beta, out);
}

// round 9
// speedup vs baseline: 7.8177x; 1.0122x over previous
#include <cuda_runtime.h>
#include <cuda_fp16.h>
#include <cstdint>
#include <math.h>

#define B_   4
#define S_   2048
#define H_   1024
#define F_   4096
#define NTOK (B_ * S_)   // 8192

// ---------------------------------------------------------------------------
// Scratch (static device globals)
// ---------------------------------------------------------------------------
__device__ __half g_xh[(size_t)NTOK * H_];
__device__ __half g_qk[(size_t)NTOK * 2 * H_];     // [8192, 2048]: q | k
__device__ __half g_s16[(size_t)B_ * S_ * S_];
__device__ __half g_a16[(size_t)NTOK * H_];
__device__ __half g_h16[(size_t)NTOK * F_];
__device__ float  g_y[(size_t)NTOK * H_];
__device__ __half g_wqkt[(size_t)2 * H_ * H_];     // [2048, 1024]: wq^T | wk^T
__device__ __half g_wvt[(size_t)H_ * H_];
__device__ __half g_w1t[(size_t)H_ * F_];
__device__ __half g_w2t[(size_t)F_ * H_];
__device__ __half g_vt[(size_t)H_ * NTOK];         // [1024, 8192] V^T, all batches
__device__ float  g_qkb[2 * H_];

// ---------------------------------------------------------------------------
// Helpers
// ---------------------------------------------------------------------------
__device__ __forceinline__ uint32_t smem_u32(const void* p) {
    uint32_t a;
    asm("{ .reg .u64 t; cvta.to.shared.u64 t, %1; cvt.u32.u64 %0, t; }" : "=r"(a) : "l"(p));
    return a;
}
__device__ __forceinline__ void cp16(uint32_t s, const void* g) {
    asm volatile("cp.async.cg.shared.global [%0], [%1], 16;" :: "r"(s), "l"(g) : "memory");
}
#define CP_COMMIT() asm volatile("cp.async.commit_group;" ::: "memory")
#define CP_WAIT2()  asm volatile("cp.async.wait_group 2;" ::: "memory")

__device__ __forceinline__ void mma16(float c[4], const uint32_t a[4], const uint32_t b[2]) {
    asm volatile("mma.sync.aligned.m16n8k16.row.col.f32.f16.f16.f32 "
                 "{%0,%1,%2,%3}, {%4,%5,%6,%7}, {%8,%9}, {%0,%1,%2,%3};"
                 : "+f"(c[0]), "+f"(c[1]), "+f"(c[2]), "+f"(c[3])
                 : "r"(a[0]), "r"(a[1]), "r"(a[2]), "r"(a[3]), "r"(b[0]), "r"(b[1]));
}
__device__ __forceinline__ void ldsm4(uint32_t r[4], uint32_t addr) {
    asm volatile("ldmatrix.sync.aligned.m8n8.x4.shared.b16 {%0,%1,%2,%3}, [%4];"
                 : "=r"(r[0]), "=r"(r[1]), "=r"(r[2]), "=r"(r[3]) : "r"(addr));
}

// ---------------------------------------------------------------------------
// FP16 tensor-core GEMM (fp32 accum), cp.async 4-stage pipeline, ldmatrix:
//   acc = alpha * A[M,K] * Bw[N,K]^T (+bias[N]) (+biasM[M]) (+res fp16) (relu)
//   outputs: C16 (fp16) if O16, C32 (fp32) if O32
// CTA tile 128x128, BK=32, 4 warps (2x2), warp tile 64x64, 128 threads.
// 2 CTAs/SM. M,N mult of 128, K mult of 32. Batched over blockIdx.z.
// Smem/stage: (128+128) rows x 80 B = 20480 B; 4 stages = 81920 B.
// ---------------------------------------------------------------------------
#define ROWB 80                                  // bytes per smem row (32 fp16 + 8 pad)
#define STAGE_B  ((128 + 128) * ROWB)            // 20480
#define NSTAGE 4
#define SMEM_B   (NSTAGE * STAGE_B)              // 81920

template <bool BIAS, bool RELU, bool RES, bool BIASM, bool O16, bool O32>
__global__ __launch_bounds__(128, 2) void tgemm(
    const __half* __restrict__ A, const __half* __restrict__ Bw,
    const float* __restrict__ bias, const __half* __restrict__ res,
    __half* __restrict__ C16, float* __restrict__ C32,
    int K, int lda, int ldb, int ldc,
    size_t sA, size_t sB, size_t sC, float alpha)
{
    extern __shared__ uint32_t smem[];
    const uint32_t sbase = smem_u32(smem);

    const int tid  = threadIdx.x;
    const int wid  = tid >> 5, lane = tid & 31;
    const int g    = lane >> 2, t4 = lane & 3;
    const int warpM = wid >> 1, warpN = wid & 1;

    const int z = blockIdx.z;
    A  += (size_t)z * sA;
    Bw += (size_t)z * sB;
    const __half* Rp = RES ? (res + (size_t)z * sC) : nullptr;

    const int n0 = blockIdx.x << 7, m0 = blockIdx.y << 7;
    const __half* Ap = A  + (size_t)m0 * lda;
    const __half* Bp = Bw + (size_t)n0 * ldb;

    const int KT = K >> 5;

    auto issue = [&](int kt) {
        const uint32_t s = sbase + (uint32_t)(kt % NSTAGE) * STAGE_B;
        const int kb = kt << 5;
#pragma unroll
        for (int j = 0; j < 4; j++) {            // A: 128 rows x 4 chunks = 512
            const int c = tid + (j << 7);
            const int row = c >> 2, ch = c & 3;
            cp16(s + (uint32_t)(row * ROWB + ch * 16),
                 Ap + (size_t)row * lda + kb + ch * 8);
        }
        const uint32_t sB2 = s + (uint32_t)(128 * ROWB);
#pragma unroll
        for (int j = 0; j < 4; j++) {            // B: 128 rows x 4 chunks = 512
            const int c = tid + (j << 7);
            const int row = c >> 2, ch = c & 3;
            cp16(sB2 + (uint32_t)(row * ROWB + ch * 16),
                 Bp + (size_t)row * ldb + kb + ch * 8);
        }
    };

    // ldmatrix per-lane source offsets (bytes)
    const int aRowOff = (((lane >> 3) & 1) << 3) + (lane & 7);
    const int aKb     = (lane >> 4) << 4;                 // 0 or 16 bytes
    const int bRowOff = ((lane >> 4) << 3) + (lane & 7);
    const int bKb     = ((lane >> 3) & 1) << 4;

    const uint32_t aLane = sbase + (uint32_t)((warpM * 64 + aRowOff) * ROWB + aKb);
    const uint32_t bLane = sbase + (uint32_t)(128 * ROWB)
        + (uint32_t)((warpN * 64 + bRowOff) * ROWB + bKb);

    float acc[4][8][4];
#pragma unroll
    for (int mt = 0; mt < 4; mt++)
#pragma unroll
        for (int nt = 0; nt < 8; nt++)
#pragma unroll
            for (int i = 0; i < 4; i++) acc[mt][nt][i] = 0.0f;

    issue(0); CP_COMMIT();
    if (KT > 1) issue(1);
    CP_COMMIT();
    if (KT > 2) issue(2);
    CP_COMMIT();

    for (int kt = 0; kt < KT; kt++) {
        CP_WAIT2();
        __syncthreads();

        if (kt + 3 < KT) issue(kt + 3);
        CP_COMMIT();

        const uint32_t stOff = (uint32_t)((kt % NSTAGE) * STAGE_B);

        // hoist ALL fragment loads (both k16 slices) ahead of the MMA burst
        uint32_t afr[2][4][4], bfr[2][8][2];
#pragma unroll
        for (int ks = 0; ks < 2; ks++) {
#pragma unroll
            for (int mt = 0; mt < 4; mt++)
                ldsm4(afr[ks][mt], aLane + stOff + (uint32_t)(mt * 16 * ROWB + ks * 32));
#pragma unroll
            for (int p = 0; p < 4; p++) {
                uint32_t r[4];
                ldsm4(r, bLane + stOff + (uint32_t)(p * 16 * ROWB + ks * 32));
                bfr[ks][2 * p][0] = r[0]; bfr[ks][2 * p][1] = r[1];
                bfr[ks][2 * p + 1][0] = r[2]; bfr[ks][2 * p + 1][1] = r[3];
            }
        }
#pragma unroll
        for (int ks = 0; ks < 2; ks++)
#pragma unroll
            for (int mt = 0; mt < 4; mt++)
#pragma unroll
                for (int nt = 0; nt < 8; nt++)
                    mma16(acc[mt][nt], afr[ks][mt], bfr[ks][nt]);
    }

    // --- fused epilogue ---
    __half* Cp16 = O16 ? (C16 + (size_t)z * sC) : nullptr;
    float*  Cp32 = O32 ? (C32 + (size_t)z * sC) : nullptr;
    const int rbase = m0 + warpM * 64;
    const int cbase = n0 + warpN * 64;
#pragma unroll
    for (int mt = 0; mt < 4; mt++) {
#pragma unroll
        for (int nt = 0; nt < 8; nt++) {
            const int col = cbase + nt * 8 + (t4 << 1);
            float bx = 0.f, by = 0.f;
            if (BIAS) {
                float2 bb = *(const float2*)(bias + col);
                bx = bb.x; by = bb.y;
            }
#pragma unroll
            for (int hh = 0; hh < 2; hh++) {
                const int row = rbase + mt * 16 + g + hh * 8;
                float v0 = acc[mt][nt][hh * 2 + 0] * alpha;
                float v1 = acc[mt][nt][hh * 2 + 1] * alpha;
                if (BIAS) { v0 += bx; v1 += by; }
                if (BIASM) { const float bm = bias[row]; v0 += bm; v1 += bm; }
                if (RES) {
                    const __half2 rr = *(const __half2*)(Rp + (size_t)row * ldc + col);
                    const float2 rf = __half22float2(rr);
                    v0 += rf.x; v1 += rf.y;
                }
                if (RELU) { v0 = fmaxf(v0, 0.f); v1 = fmaxf(v1, 0.f); }
                if (O16)
                    *(__half2*)(Cp16 + (size_t)row * ldc + col) = __floats2half2_rn(v0, v1);
                if (O32) {
                    float2 o; o.x = v0; o.y = v1;
                    *(float2*)(Cp32 + (size_t)row * ldc + col) = o;
                }
            }
        }
    }
}

// ---------------------------------------------------------------------------
// x (fp32) -> fp16
// ---------------------------------------------------------------------------
__global__ __launch_bounds__(256) void tohalf_k(const float* __restrict__ in,
                                                __half* __restrict__ out)
{
    const size_t i = ((size_t)blockIdx.x * 256 + threadIdx.x) * 4;
    float4 v = *(const float4*)(in + i);
    __half2* o = (__half2*)(out + i);
    o[0] = __floats2half2_rn(v.x, v.y);
    o[1] = __floats2half2_rn(v.z, v.w);
}

// ---------------------------------------------------------------------------
// Concat two H_-vectors (bias) into one 2H_ vector
// ---------------------------------------------------------------------------
__global__ __launch_bounds__(256) void catbias_k(const float* __restrict__ a,
                                                 const float* __restrict__ b,
                                                 float* __restrict__ out)
{
    const int i = blockIdx.x * 256 + threadIdx.x;
    out[i] = (i < H_) ? a[i] : b[i - H_];
}

// ---------------------------------------------------------------------------
// Transpose fp32 src [R,C] -> fp16 dst [C,R]
// ---------------------------------------------------------------------------
__global__ __launch_bounds__(256) void transpose_k(const float* __restrict__ src,
                                                   __half* __restrict__ dst, int R, int C)
{
    __shared__ float t[32][33];
    const int bx = blockIdx.x << 5, by = blockIdx.y << 5;
    const int tx = threadIdx.x & 31, ty = (threadIdx.x >> 5) << 2;
#pragma unroll
    for (int j = 0; j < 4; j++)
        t[ty + j][tx] = src[(size_t)(by + ty + j) * C + bx + tx];
    __syncthreads();
#pragma unroll
    for (int j = 0; j < 4; j++)
        dst[(size_t)(bx + ty + j) * R + by + tx] = __float2half_rn(t[tx][ty + j]);
}

// ---------------------------------------------------------------------------
// Row softmax (S_ wide) on fp16 scores with fp32 mask; in-place fp16
// ---------------------------------------------------------------------------
__global__ __launch_bounds__(256) void softmax_k(__half* __restrict__ s,
                                                 const float* __restrict__ mask)
{
    const int row = blockIdx.x;
    const int q   = row & (S_ - 1);
    __half2* p = (__half2*)(s + (size_t)row * S_);
    const float* mrow = mask + (size_t)q * S_;
    const int tid = threadIdx.x;
    __shared__ float red[256];

    float vals[8];
    float vmax = -3.0e38f;
#pragma unroll
    for (int i = 0; i < 4; i++) {
        const int idx = tid + i * 256;          // half2 index
        const float2 v2 = __half22float2(p[idx]);
        const float m0 = mrow[idx * 2], m1 = mrow[idx * 2 + 1];
        const float a = v2.x + m0, b = v2.y + m1;
        vals[2 * i] = a; vals[2 * i + 1] = b;
        vmax = fmaxf(vmax, fmaxf(a, b));
    }
    red[tid] = vmax; __syncthreads();
    for (int o = 128; o > 0; o >>= 1) {
        if (tid < o) red[tid] = fmaxf(red[tid], red[tid + o]);
        __syncthreads();
    }
    vmax = red[0]; __syncthreads();
    float sum = 0.0f;
#pragma unroll
    for (int i = 0; i < 8; i++) { const float e = __expf(vals[i] - vmax); vals[i] = e; sum += e; }
    red[tid] = sum; __syncthreads();
    for (int o = 128; o > 0; o >>= 1) {
        if (tid < o) red[tid] += red[tid + o];
        __syncthreads();
    }
    const float inv = 1.0f / red[0];
#pragma unroll
    for (int i = 0; i < 4; i++)
        p[tid + i * 256] = __floats2half2_rn(vals[2 * i] * inv, vals[2 * i + 1] * inv);
}

// ---------------------------------------------------------------------------
// LayerNorm (H_=1024)
// ---------------------------------------------------------------------------
__global__ __launch_bounds__(256) void ln_k(const float* __restrict__ y,
                                            const float* __restrict__ gamma,
                                            const float* __restrict__ beta,
                                            float* __restrict__ out)
{
    const int row = blockIdx.x;
    const float4* p4 = (const float4*)(y + (size_t)row * H_);
    const int tid = threadIdx.x;
    __shared__ float rs[256], rq[256];

    const float4 v = p4[tid];
    rs[tid] = v.x + v.y + v.z + v.w;
    rq[tid] = v.x * v.x + v.y * v.y + v.z * v.z + v.w * v.w;
    __syncthreads();
    for (int o = 128; o > 0; o >>= 1) {
        if (tid < o) { rs[tid] += rs[tid + o]; rq[tid] += rq[tid + o]; }
        __syncthreads();
    }
    const float mu  = rs[0] * (1.0f / H_);
    const float var = rq[0] * (1.0f / H_) - mu * mu;
    const float inv = rsqrtf(var + 1e-5f);
    const float4 g = ((const float4*)gamma)[tid];
    const float4 b = ((const float4*)beta)[tid];
    float4 o;
    o.x = (v.x - mu) * inv * g.x + b.x;
    o.y = (v.y - mu) * inv * g.y + b.y;
    o.z = (v.z - mu) * inv * g.z + b.z;
    o.w = (v.w - mu) * inv * g.w + b.w;
    ((float4*)(out + (size_t)row * H_))[tid] = o;
}

// ---------------------------------------------------------------------------
// Launch   (harness issues 2 launches before these; ncu -s 5 -c 1 captures
//           overall launch #6 = OUR launch #4 = the V^T tgemm)
// ---------------------------------------------------------------------------
extern "C" void kernel_launch(void* const* d_in, const int* in_sizes, int n_in,
                              void* d_out, int out_size)
{
    const float* x     = (const float*)d_in[0];
    const float* mask  = (const float*)d_in[1];
    const float* qW    = (const float*)d_in[2];
    const float* qb    = (const float*)d_in[3];
    const float* kW    = (const float*)d_in[4];
    const float* kb    = (const float*)d_in[5];
    const float* vW    = (const float*)d_in[6];
    const float* vb    = (const float*)d_in[7];
    const float* w1    = (const float*)d_in[8];
    const float* b1    = (const float*)d_in[9];
    const float* w2    = (const float*)d_in[10];
    const float* b2    = (const float*)d_in[11];
    const float* gamma = (const float*)d_in[12];
    const float* beta  = (const float*)d_in[13];
    float* out = (float*)d_out;

    __half *xh, *qk, *s16, *a16, *h16, *wqkt, *wvt, *w1t, *w2t, *vt;
    float *yp, *qkb;
    cudaGetSymbolAddress((void**)&xh, g_xh);
    cudaGetSymbolAddress((void**)&qk, g_qk);
    cudaGetSymbolAddress((void**)&s16, g_s16);
    cudaGetSymbolAddress((void**)&a16, g_a16);
    cudaGetSymbolAddress((void**)&h16, g_h16);
    cudaGetSymbolAddress((void**)&yp, g_y);
    cudaGetSymbolAddress((void**)&wqkt, g_wqkt);
    cudaGetSymbolAddress((void**)&wvt, g_wvt);
    cudaGetSymbolAddress((void**)&w1t, g_w1t);
    cudaGetSymbolAddress((void**)&w2t, g_w2t);
    cudaGetSymbolAddress((void**)&vt, g_vt);
    cudaGetSymbolAddress((void**)&qkb, g_qkb);

    cudaFuncSetAttribute((const void*)tgemm<true,  false, false, false, true,  false>,
                         cudaFuncAttributeMaxDynamicSharedMemorySize, SMEM_B);
    cudaFuncSetAttribute((const void*)tgemm<false, false, false, true,  true,  false>,
                         cudaFuncAttributeMaxDynamicSharedMemorySize, SMEM_B);
    cudaFuncSetAttribute((const void*)tgemm<false, false, false, false, true,  false>,
                         cudaFuncAttributeMaxDynamicSharedMemorySize, SMEM_B);
    cudaFuncSetAttribute((const void*)tgemm<true,  true,  false, false, true,  false>,
                         cudaFuncAttributeMaxDynamicSharedMemorySize, SMEM_B);
    cudaFuncSetAttribute((const void*)tgemm<true,  false, true,  false, false, true >,
                         cudaFuncAttributeMaxDynamicSharedMemorySize, SMEM_B);

    const dim3 blk(256);
    const dim3 gblk(128);

    // 1: x -> fp16
    tohalf_k<<<(NTOK * H_) / 1024, blk>>>(x, xh);
    // 2: transpose vW (needed by #4)
    transpose_k<<<dim3(H_ / 32, H_ / 32, 1), blk>>>(vW, wvt, H_, H_);
    // 3: transpose qW (prep for #7)
    transpose_k<<<dim3(H_ / 32, H_ / 32, 1), blk>>>(qW, wqkt, H_, H_);

    // 4: V^T = wv^T @ x^T + vb -> vt fp16 [1024, 8192]   <-- ncu capture
    tgemm<false, false, false, true, true, false>
        <<<dim3(NTOK / 128, H_ / 128, 1), gblk, SMEM_B>>>(
        wvt, xh, vb, nullptr, vt, nullptr,
        H_, H_, H_, NTOK, 0, 0, 0, 1.0f);

    // 5: transpose kW; 6: concat q/k biases
    transpose_k<<<dim3(H_ / 32, H_ / 32, 1), blk>>>(kW, wqkt + (size_t)H_ * H_, H_, H_);
    catbias_k<<<(2 * H_) / 256, blk>>>(qb, kb, qkb);

    // 7: fused Q|K projection -> qk fp16 [8192, 2048]
    tgemm<true, false, false, false, true, false>
        <<<dim3(2 * H_ / 128, NTOK / 128, 1), gblk, SMEM_B>>>(
        xh, wqkt, qkb, nullptr, qk, nullptr,
        H_, H_, H_, 2 * H_, 0, 0, 0, 1.0f);

    // 8,9: FFN weight transposes
    transpose_k<<<dim3(F_ / 32, H_ / 32, 1), blk>>>(w1, w1t, H_, F_);
    transpose_k<<<dim3(H_ / 32, F_ / 32, 1), blk>>>(w2, w2t, F_, H_);

    // 10: scores = q @ k^T / sqrt(H) -> s16, per batch
    tgemm<false, false, false, false, true, false>
        <<<dim3(S_ / 128, S_ / 128, B_), gblk, SMEM_B>>>(
        qk, qk + H_, nullptr, nullptr, s16, nullptr,
        H_, 2 * H_, 2 * H_, S_,
        (size_t)S_ * 2 * H_, (size_t)S_ * 2 * H_, (size_t)S_ * S_, 0.03125f);

    // 11: softmax in place on fp16
    softmax_k<<<NTOK, blk>>>(s16, mask);

    // 12: attn = a @ v -> a16 fp16, per batch
    tgemm<false, false, false, false, true, false>
        <<<dim3(H_ / 128, S_ / 128, B_), gblk, SMEM_B>>>(
        s16, vt, nullptr, nullptr, a16, nullptr,
        S_, S_, NTOK, H_,
        (size_t)S_ * S_, (size_t)S_, (size_t)S_ * H_, 1.0f);

    // 13: FFN1: h = relu(attn @ w1 + b1) -> h16
    tgemm<true, true, false, false, true, false>
        <<<dim3(F_ / 128, NTOK / 128, 1), gblk, SMEM_B>>>(
        a16, w1t, b1, nullptr, h16, nullptr,
        H_, H_, H_, F_, 0, 0, 0, 1.0f);

    // 14: FFN2: y = attn16 + h @ w2 + b2 -> fp32
    tgemm<true, false, true, false, false, true>
        <<<dim3(H_ / 128, NTOK / 128, 1), gblk, SMEM_B>>>(
        h16, w2t, b2, a16, nullptr, yp,
        F_, F_, F_, H_, 0, 0, 0, 1.0f);

    // 15: LayerNorm
    ln_k<<<NTOK, blk>>>(yp, gamma, beta, out);
}